// round 12
// baseline (speedup 1.0000x reference)
#include <cuda_runtime.h>
#include <cuda_bf16.h>
#include <cstdint>
#include <math.h>

#define RB   1024
#define RD   128
#define RC   256
#define RM   100000
#define RMP  100096          // M padded to 128
#define RK   50
#define NK   96              // candidates per segment
#define TSEG 4               // segments per row
#define SEGLEN (RM/TSEG)     // 25000 (multiple of 8)
#define NKT  (NK*TSEG)       // 384 candidates per row total
#define RNR  (RB*RK)         // 51200
#define KE1  768             // 3-term split K for gemm1
#define INV_T 14.285714285714286f

// ---------------- device scratch ----------------
__device__ __align__(256) float g_qn[RB*RD];
__device__ __align__(256) float g_kn[(size_t)RMP*RD];   // zero-init
__device__ __align__(256) __nv_bfloat16 g_qh[RB*RD];
__device__ __align__(256) __nv_bfloat16 g_kh[(size_t)RMP*RD];  // padded rows stay 0
__device__ __align__(256) __nv_bfloat16 g_w1t[(size_t)RC*KE1]; // [c][k] split: hi,lo,hi
__device__ __align__(256) int   g_sess[RMP];
__device__ __align__(256) __nv_bfloat16 g_simsb[(size_t)RB*RMP];
__device__ __align__(256) int   g_candi[RB*NKT];
__device__ __align__(256) float g_topv[RB*RK];
__device__ __align__(256) int   g_topi[RB*RK];
__device__ __align__(256) float g_w[RNR];
__device__ __align__(256) int   g_tgt[RNR];
__device__ __align__(256) int   g_ixs[RNR];
__device__ __align__(256) int   g_used[RB];
__device__ __align__(256) float g_H[(size_t)RNR*RC];
__device__ __align__(256) float g_S[RB*RC];

#define SPAD 40     // bf16 per smem row (32 data + 8 pad)

// ---------------- SIMT projection + l2norm, exact fp32 (order-preserving vectorized) ----------------
#define KP_ROWS 32
__global__ __launch_bounds__(128) void proj_kernel(
    const float* __restrict__ X, const float* __restrict__ W,
    const float* __restrict__ bias, float* __restrict__ out,
    __nv_bfloat16* __restrict__ out_bf)
{
    __shared__ float xs[KP_ROWS][RD];
    __shared__ float os[KP_ROWS][RD+1];
    __shared__ float n4[KP_ROWS][4];
    int tid = threadIdx.x;
    size_t base = (size_t)blockIdx.x * KP_ROWS;
    #pragma unroll
    for (int rr = 0; rr < KP_ROWS; rr++)
        xs[rr][tid] = X[(base+rr)*RD + tid];
    __syncthreads();
    float acc[KP_ROWS];
    float bv = bias[tid];
    #pragma unroll
    for (int rr = 0; rr < KP_ROWS; rr++) acc[rr] = bv;
    // identical fmaf chain order (ascending d) — LDS vectorized only
    for (int d = 0; d < RD; d += 4){
        float w0 = W[(d+0)*RD + tid];
        float w1 = W[(d+1)*RD + tid];
        float w2 = W[(d+2)*RD + tid];
        float w3 = W[(d+3)*RD + tid];
        #pragma unroll
        for (int rr = 0; rr < KP_ROWS; rr++){
            float4 xv = *(const float4*)&xs[rr][d];
            float a = acc[rr];
            a = fmaf(xv.x, w0, a);
            a = fmaf(xv.y, w1, a);
            a = fmaf(xv.z, w2, a);
            a = fmaf(xv.w, w3, a);
            acc[rr] = a;
        }
    }
    #pragma unroll
    for (int rr = 0; rr < KP_ROWS; rr++) os[rr][tid] = acc[rr];
    __syncthreads();
    {
        int rr = tid >> 2, q = tid & 3;
        float s = 0.f;
        #pragma unroll
        for (int j = 0; j < 32; j++){ float v = os[rr][q*32 + j]; s = fmaf(v, v, s); }
        n4[rr][q] = s;
    }
    __syncthreads();
    if (tid < KP_ROWS){
        float t = n4[tid][0] + n4[tid][1] + n4[tid][2] + n4[tid][3];
        n4[tid][0] = 1.0f / fmaxf(sqrtf(t), 1e-12f);
    }
    __syncthreads();
    #pragma unroll
    for (int rr = 0; rr < KP_ROWS; rr++){
        float v = os[rr][tid] * n4[rr][0];
        out[(base+rr)*RD + tid] = v;
        out_bf[(base+rr)*RD + tid] = __float2bfloat16(v);
    }
}

__global__ void sess_pad_kernel(const int* __restrict__ sq){
    int i = blockIdx.x*256 + threadIdx.x;
    if (i < RMP) g_sess[i] = (i < RM) ? sq[i] : -1;
}

// ---------------- W1 3-term split, transposed to [c][k]: chunks hi, lo, hi ----------------
__global__ __launch_bounds__(256) void w1split_kernel(const float* __restrict__ W1){
    int idx = blockIdx.x*256 + threadIdx.x;   // k*256 + c
    if (idx >= RC*RC) return;
    int k = idx >> 8, c = idx & 255;
    float x = W1[idx];
    __nv_bfloat16 hi = __float2bfloat16(x);
    __nv_bfloat16 lo = __float2bfloat16(x - __bfloat162float(hi));
    size_t b = (size_t)c*KE1 + k;
    g_w1t[b] = hi; g_w1t[b+256] = lo; g_w1t[b+512] = hi;
}

// ---------------- sims = qh @ kh^T via bf16 mma, K=128; bf16 output, staged stores ----------------
__global__ __launch_bounds__(256) void sims_mma_kernel(const int* __restrict__ sessid)
{
    __shared__ __nv_bfloat16 sAB[2*128*SPAD];
    __nv_bfloat16 (*As)[SPAD] = (__nv_bfloat16(*)[SPAD])sAB;
    __nv_bfloat16 (*Bs)[SPAD] = (__nv_bfloat16(*)[SPAD])(sAB + 128*SPAD);
    __shared__ int sids[128];
    __shared__ int msess[128];

    int tid  = threadIdx.x;
    int lane = tid & 31;
    int wid  = tid >> 5;
    int wm   = wid >> 2;
    int wn   = wid & 3;
    int m0 = blockIdx.x * 128;
    int b0 = blockIdx.y * 128;

    if (tid < 128){ sids[tid] = sessid[b0 + tid]; msess[tid] = g_sess[m0 + tid]; }

    float acc[4][4][4];
    #pragma unroll
    for (int i = 0; i < 4; i++)
        #pragma unroll
        for (int j = 0; j < 4; j++)
            #pragma unroll
            for (int r = 0; r < 4; r++) acc[i][j][r] = 0.f;

    const __nv_bfloat16* qbase = g_qh + (size_t)b0*RD;
    const __nv_bfloat16* kbase = g_kh + (size_t)m0*RD;
    int s0 = tid, s1 = tid + 256;
    int ra0 = s0 >> 2, ca0 = (s0 & 3) * 8;
    int ra1 = s1 >> 2, ca1 = (s1 & 3) * 8;

    uint4 pa0 = *(const uint4*)(qbase + (size_t)ra0*RD + ca0);
    uint4 pa1 = *(const uint4*)(qbase + (size_t)ra1*RD + ca1);
    uint4 pb0 = *(const uint4*)(kbase + (size_t)ra0*RD + ca0);
    uint4 pb1 = *(const uint4*)(kbase + (size_t)ra1*RD + ca1);

    for (int kc = 0; kc < RD; kc += 32){
        __syncthreads();
        *(uint4*)&As[ra0][ca0] = pa0;
        *(uint4*)&As[ra1][ca1] = pa1;
        *(uint4*)&Bs[ra0][ca0] = pb0;
        *(uint4*)&Bs[ra1][ca1] = pb1;
        __syncthreads();
        int kn = kc + 32;
        if (kn < RD){
            pa0 = *(const uint4*)(qbase + (size_t)ra0*RD + kn + ca0);
            pa1 = *(const uint4*)(qbase + (size_t)ra1*RD + kn + ca1);
            pb0 = *(const uint4*)(kbase + (size_t)ra0*RD + kn + ca0);
            pb1 = *(const uint4*)(kbase + (size_t)ra1*RD + kn + ca1);
        }
        #pragma unroll
        for (int ks = 0; ks < 2; ks++){
            int kk = ks * 16;
            uint32_t af[4][4], bf[4][2];
            #pragma unroll
            for (int mi = 0; mi < 4; mi++){
                uint32_t addr = (uint32_t)__cvta_generic_to_shared(
                    &As[wm*64 + mi*16 + (lane & 15)][kk + (lane >> 4)*8]);
                asm volatile("ldmatrix.sync.aligned.m8n8.x4.shared.b16 {%0,%1,%2,%3}, [%4];"
                    : "=r"(af[mi][0]), "=r"(af[mi][1]), "=r"(af[mi][2]), "=r"(af[mi][3])
                    : "r"(addr));
            }
            #pragma unroll
            for (int ni = 0; ni < 4; ni++){
                uint32_t addr = (uint32_t)__cvta_generic_to_shared(
                    &Bs[wn*32 + ni*8 + (lane & 7)][kk + ((lane >> 3) & 1)*8]);
                asm volatile("ldmatrix.sync.aligned.m8n8.x2.shared.b16 {%0,%1}, [%2];"
                    : "=r"(bf[ni][0]), "=r"(bf[ni][1]) : "r"(addr));
            }
            #pragma unroll
            for (int mi = 0; mi < 4; mi++)
                #pragma unroll
                for (int ni = 0; ni < 4; ni++){
                    asm volatile(
                        "mma.sync.aligned.m16n8k16.row.col.f32.bf16.bf16.f32 "
                        "{%0,%1,%2,%3}, {%4,%5,%6,%7}, {%8,%9}, {%0,%1,%2,%3};"
                        : "+f"(acc[mi][ni][0]), "+f"(acc[mi][ni][1]),
                          "+f"(acc[mi][ni][2]), "+f"(acc[mi][ni][3])
                        : "r"(af[mi][0]), "r"(af[mi][1]), "r"(af[mi][2]), "r"(af[mi][3]),
                          "r"(bf[ni][0]), "r"(bf[ni][1]));
                }
        }
    }

    // epilogue: mask + stage 64-row halves in smem, then coalesced 16B stores
    const unsigned short NEGINF = 0xFF80;
    __nv_bfloat16* stg = sAB;     // [64][136]
    #pragma unroll
    for (int p = 0; p < 2; p++){
        __syncthreads();
        if (wm == p){
            #pragma unroll
            for (int mi = 0; mi < 4; mi++){
                #pragma unroll
                for (int h = 0; h < 2; h++){
                    int lr = mi*16 + (lane >> 2) + h*8;      // 0..63
                    int sid = sids[p*64 + lr];
                    #pragma unroll
                    for (int ni = 0; ni < 4; ni++){
                        int cl = wn*32 + ni*8 + (lane & 3)*2;
                        __nv_bfloat162 hv = __float22bfloat162_rn(
                            make_float2(acc[mi][ni][h*2+0], acc[mi][ni][h*2+1]));
                        unsigned int u = *(unsigned int*)&hv;
                        if (msess[cl]   == sid) u = (u & 0xFFFF0000u) | NEGINF;
                        if (msess[cl+1] == sid) u = (u & 0x0000FFFFu) | ((unsigned)NEGINF << 16);
                        *(unsigned int*)&stg[lr*136 + cl] = u;
                    }
                }
            }
        }
        __syncthreads();
        int lrow = tid >> 2, t4 = tid & 3;
        #pragma unroll
        for (int i = 0; i < 4; i++){
            int seg = t4*4 + i;                              // 0..15, 8 bf16 each
            uint4 v = *(uint4*)&stg[lrow*136 + seg*8];
            *(uint4*)&g_simsb[(size_t)(b0 + p*64 + lrow)*RMP + m0 + seg*8] = v;
        }
    }
}

// ---------------- streaming top-NK per row segment over bf16 sims ----------------
#define TK_CAP 3072
#define TK_TPB 256

__device__ __forceinline__ bool better(float v, int m, float bv, int bm){
    return (v > bv) || (v == bv && m < bm);
}

__device__ void topk_flush(float* sval, int* sidx, int* cnt, float* thr,
                           float* selv, int* seli, float* wv, int* wm, int* wp, int tid)
{
    int n = *cnt; if (n > TK_CAP) n = TK_CAP;
    __syncthreads();
    for (int r = 0; r < NK; r++){
        float bv = -INFINITY; int bm = 0x7fffffff; int bp = -1;
        for (int i = tid; i < n; i += TK_TPB){
            float v = sval[i]; int m = sidx[i];
            if (v > -3.0e38f && better(v, m, bv, bm)){ bv = v; bm = m; bp = i; }
        }
        #pragma unroll
        for (int o = 16; o > 0; o >>= 1){
            float ov = __shfl_down_sync(0xffffffffu, bv, o);
            int   om = __shfl_down_sync(0xffffffffu, bm, o);
            int   op = __shfl_down_sync(0xffffffffu, bp, o);
            if (op >= 0 && (bp < 0 || better(ov, om, bv, bm))){ bv = ov; bm = om; bp = op; }
        }
        if ((tid & 31) == 0){ wv[tid >> 5] = bv; wm[tid >> 5] = bm; wp[tid >> 5] = bp; }
        __syncthreads();
        if (tid == 0){
            float v2 = wv[0]; int m2 = wm[0]; int p2 = wp[0];
            #pragma unroll
            for (int q = 1; q < 8; q++)
                if (wp[q] >= 0 && (p2 < 0 || better(wv[q], wm[q], v2, m2))){ v2 = wv[q]; m2 = wm[q]; p2 = wp[q]; }
            selv[r] = (p2 >= 0) ? v2 : -INFINITY;
            seli[r] = (p2 >= 0) ? m2 : -1;
            if (p2 >= 0) sval[p2] = -INFINITY;
        }
        __syncthreads();
    }
    if (tid < NK){ sval[tid] = selv[tid]; sidx[tid] = (seli[tid] >= 0) ? seli[tid] : 0x7ffffffe; }
    if (tid == 0){ *cnt = NK; *thr = selv[NK-1]; }
    __syncthreads();
}

__global__ __launch_bounds__(TK_TPB) void topk_kernel()
{
    int blk = blockIdx.x;
    int b   = blk / TSEG;
    int seg = blk % TSEG;
    int tid = threadIdx.x;
    __shared__ float sval[TK_CAP];
    __shared__ int   sidx[TK_CAP];
    __shared__ float selv[NK];
    __shared__ int   seli[NK];
    __shared__ float wv[8];
    __shared__ int   wm[8];
    __shared__ int   wp[8];
    __shared__ int   cnt;
    __shared__ float thr;
    if (tid == 0){ cnt = 0; thr = -INFINITY; }
    __syncthreads();
    int sbase = seg * SEGLEN;
    const __nv_bfloat16* row = g_simsb + (size_t)b * RMP + sbase;
    for (int base = 0; base < SEGLEN; base += 2048){
        int i = base + tid*8;
        float t = thr;
        if (i < SEGLEN){  // SEGLEN % 8 == 0
            uint4 pk = *(const uint4*)(row + i);
            unsigned int us[4] = {pk.x, pk.y, pk.z, pk.w};
            #pragma unroll
            for (int q = 0; q < 4; q++){
                __nv_bfloat162 h2 = *(__nv_bfloat162*)&us[q];
                float2 fv = __bfloat1622float2(h2);
                if (fv.x >= t && fv.x > -3.0e38f){ int p = atomicAdd(&cnt,1); if (p < TK_CAP){ sval[p]=fv.x; sidx[p]=sbase+i+q*2;   } }
                if (fv.y >= t && fv.y > -3.0e38f){ int p = atomicAdd(&cnt,1); if (p < TK_CAP){ sval[p]=fv.y; sidx[p]=sbase+i+q*2+1; } }
            }
        }
        __syncthreads();
        if (cnt > TK_CAP - 2048)
            topk_flush(sval, sidx, &cnt, &thr, selv, seli, wv, wm, wp, tid);
        __syncthreads();
    }
    topk_flush(sval, sidx, &cnt, &thr, selv, seli, wv, wm, wp, tid);
    if (tid < NK)
        g_candi[(b*TSEG + seg)*NK + tid] = seli[tid];
}

// ---------------- fp64 refinement of the NKT candidates + exact top-50 ----------------
__global__ __launch_bounds__(NKT) void refine_kernel()
{
    int b = blockIdx.x, k = threadIdx.x;
    __shared__ float q[RD];
    __shared__ float rv[NKT];
    __shared__ int   ri[NKT];
    for (int t = k; t < RD; t += NKT) q[t] = g_qn[b*RD + t];
    __syncthreads();
    int idx = g_candi[b*NKT + k];
    float fv = -INFINITY;
    if (idx >= 0){
        const float* kr = &g_kn[(size_t)idx*RD];
        double s = 0.0;
        #pragma unroll 8
        for (int d = 0; d < RD; d++) s += (double)q[d] * (double)kr[d];
        fv = (float)s;
    }
    rv[k] = fv;
    ri[k] = (idx >= 0) ? idx : (0x40000000 + k);   // unique sentinel per slot
    __syncthreads();
    float mv = rv[k]; int mi = ri[k];
    int rank = 0;
    for (int j = 0; j < NKT; j++){
        float v = rv[j]; int m = ri[j];
        rank += ((v > mv) || (v == mv && m < mi)) ? 1 : 0;
    }
    if (rank < RK){
        g_topv[b*RK + rank] = mv;
        g_topi[b*RK + rank] = (mi >= 0x40000000) ? -1 : mi;
    }
}

// ---------------- softmax attn + context + gather metadata ----------------
__global__ __launch_bounds__(RD) void attn_ctx_kernel(
    const float* __restrict__ fq, const int* __restrict__ tq,
    const float* __restrict__ fb_ctx, float* __restrict__ out_ctx,
    float* __restrict__ out_used)
{
    int b = blockIdx.x, tid = threadIdx.x;
    __shared__ float v[RK];
    __shared__ int   ixs[RK];
    __shared__ float w[RK];
    __shared__ int   uflag;
    if (tid < RK){ v[tid] = g_topv[b*RK + tid]; int id = g_topi[b*RK + tid]; ixs[tid] = (id >= 0) ? id : 0;
                   g_ixs[b*RK + tid] = ixs[tid];
                   g_tgt[b*RK + tid] = (id >= 0) ? max(tq[ixs[tid]], 0) : 0; }
    __syncthreads();
    if (tid == 0){
        float mx = -INFINITY; int u = 0;
        for (int k = 0; k < RK; k++){
            float vk = v[k];
            if (vk > -1e30f){ u = 1; if (vk > mx) mx = vk; }
        }
        float s = 0.f;
        for (int k = 0; k < RK; k++){
            float vk = v[k];
            float wk = (vk > -1e30f) ? expf((vk - mx) * INV_T) : 0.f;
            w[k] = wk; s += wk;
        }
        float inv = 1.0f / fmaxf(s, 1e-12f);
        for (int k = 0; k < RK; k++) w[k] *= inv;
        uflag = u;
        g_used[b] = u;
        out_used[b] = u ? 1.0f : 0.0f;
    }
    __syncthreads();
    if (tid < RK) g_w[b*RK + tid] = w[tid];
    float c = 0.f;
    for (int k = 0; k < RK; k++){
        float wk = w[k];
        if (wk != 0.f) c = fmaf(wk, fq[(size_t)ixs[k]*RD + tid], c);
    }
    out_ctx[b*RD + tid] = uflag ? c : fb_ctx[tid];
}

// ---------------- gemm1 via bf16 mma, 3-term split (K=768) ----------------
__device__ __forceinline__ uint4 lda8_split(
    const float* __restrict__ fq, const float* __restrict__ item_emb,
    int rowf, int rowt, int kg)   // kg = global col in [0, KE1)
{
    int t = kg >> 8, sc = kg & 255;
    const float* src = (sc < 128) ? (fq + (size_t)rowf*RD + sc)
                                  : (item_emb + (size_t)rowt*RD + (sc - 128));
    float4 u = *(const float4*)src;
    float4 v = *(const float4*)(src + 4);
    float xs[8] = {u.x,u.y,u.z,u.w,v.x,v.y,v.z,v.w};
    bool lo = (t == 2);
    uint4 r; unsigned short* p = (unsigned short*)&r;
    #pragma unroll
    for (int i = 0; i < 8; i++){
        __nv_bfloat16 hi = __float2bfloat16(xs[i]);
        p[i] = lo ? __bfloat16_as_ushort(__float2bfloat16(xs[i] - __bfloat162float(hi)))
                  : __bfloat16_as_ushort(hi);
    }
    return r;
}

__global__ __launch_bounds__(256) void gemm1_mma_kernel(
    const float* __restrict__ fq, const float* __restrict__ item_emb,
    const float* __restrict__ b1)
{
    __shared__ __nv_bfloat16 As[128][SPAD];
    __shared__ __nv_bfloat16 Bs[128][SPAD];
    __shared__ int   rid[128];
    __shared__ int   tgd[128];
    __shared__ float wrow[128];

    int tid  = threadIdx.x;
    int lane = tid & 31;
    int wid  = tid >> 5;
    int wm   = wid >> 2;
    int wn   = wid & 3;
    int c0  = blockIdx.x * 128;
    int nr0 = blockIdx.y * 128;

    if (tid < 128){
        rid[tid]  = g_ixs[nr0 + tid];
        tgd[tid]  = g_tgt[nr0 + tid];
        wrow[tid] = g_w[nr0 + tid];
    }
    __syncthreads();

    float acc[4][4][4];
    #pragma unroll
    for (int i = 0; i < 4; i++)
        #pragma unroll
        for (int j = 0; j < 4; j++)
            #pragma unroll
            for (int r = 0; r < 4; r++) acc[i][j][r] = 0.f;

    int s0 = tid, s1 = tid + 256;
    int ra0 = s0 >> 2, ca0 = (s0 & 3) * 8;
    int ra1 = s1 >> 2, ca1 = (s1 & 3) * 8;
    const __nv_bfloat16* wbase = g_w1t + (size_t)c0*KE1;

    uint4 pa0 = lda8_split(fq, item_emb, rid[ra0], tgd[ra0], ca0);
    uint4 pa1 = lda8_split(fq, item_emb, rid[ra1], tgd[ra1], ca1);
    uint4 pb0 = *(const uint4*)(wbase + (size_t)ra0*KE1 + ca0);
    uint4 pb1 = *(const uint4*)(wbase + (size_t)ra1*KE1 + ca1);

    for (int kc = 0; kc < KE1; kc += 32){
        __syncthreads();
        *(uint4*)&As[ra0][ca0] = pa0;
        *(uint4*)&As[ra1][ca1] = pa1;
        *(uint4*)&Bs[ra0][ca0] = pb0;
        *(uint4*)&Bs[ra1][ca1] = pb1;
        __syncthreads();
        int kn = kc + 32;
        if (kn < KE1){
            pa0 = lda8_split(fq, item_emb, rid[ra0], tgd[ra0], kn + ca0);
            pa1 = lda8_split(fq, item_emb, rid[ra1], tgd[ra1], kn + ca1);
            pb0 = *(const uint4*)(wbase + (size_t)ra0*KE1 + kn + ca0);
            pb1 = *(const uint4*)(wbase + (size_t)ra1*KE1 + kn + ca1);
        }
        #pragma unroll
        for (int ks = 0; ks < 2; ks++){
            int kk = ks * 16;
            uint32_t af[4][4], bf[4][2];
            #pragma unroll
            for (int mi = 0; mi < 4; mi++){
                uint32_t addr = (uint32_t)__cvta_generic_to_shared(
                    &As[wm*64 + mi*16 + (lane & 15)][kk + (lane >> 4)*8]);
                asm volatile("ldmatrix.sync.aligned.m8n8.x4.shared.b16 {%0,%1,%2,%3}, [%4];"
                    : "=r"(af[mi][0]), "=r"(af[mi][1]), "=r"(af[mi][2]), "=r"(af[mi][3])
                    : "r"(addr));
            }
            #pragma unroll
            for (int ni = 0; ni < 4; ni++){
                uint32_t addr = (uint32_t)__cvta_generic_to_shared(
                    &Bs[wn*32 + ni*8 + (lane & 7)][kk + ((lane >> 3) & 1)*8]);
                asm volatile("ldmatrix.sync.aligned.m8n8.x2.shared.b16 {%0,%1}, [%2];"
                    : "=r"(bf[ni][0]), "=r"(bf[ni][1]) : "r"(addr));
            }
            #pragma unroll
            for (int mi = 0; mi < 4; mi++)
                #pragma unroll
                for (int ni = 0; ni < 4; ni++){
                    asm volatile(
                        "mma.sync.aligned.m16n8k16.row.col.f32.bf16.bf16.f32 "
                        "{%0,%1,%2,%3}, {%4,%5,%6,%7}, {%8,%9}, {%0,%1,%2,%3};"
                        : "+f"(acc[mi][ni][0]), "+f"(acc[mi][ni][1]),
                          "+f"(acc[mi][ni][2]), "+f"(acc[mi][ni][3])
                        : "r"(af[mi][0]), "r"(af[mi][1]), "r"(af[mi][2]), "r"(af[mi][3]),
                          "r"(bf[ni][0]), "r"(bf[ni][1]));
                }
        }
    }

    #pragma unroll
    for (int mi = 0; mi < 4; mi++){
        int rl0 = wm*64 + mi*16 + (lane >> 2);
        #pragma unroll
        for (int ni = 0; ni < 4; ni++){
            int cl = wn*32 + ni*8 + (lane & 3)*2;
            int c = c0 + cl;
            float bb0 = b1[c], bb1 = b1[c+1];
            #pragma unroll
            for (int h = 0; h < 2; h++){
                int rr = rl0 + h*8;
                float x0 = acc[mi][ni][h*2+0] + bb0;
                float x1 = acc[mi][ni][h*2+1] + bb1;
                float g0 = 0.5f * x0 * (1.0f + erff(x0 * 0.70710678118654752f));
                float g1 = 0.5f * x1 * (1.0f + erff(x1 * 0.70710678118654752f));
                float wk = wrow[rr];
                float2 v; v.x = wk * g0; v.y = wk * g1;
                *(float2*)&g_H[(size_t)(nr0 + rr)*RC + c] = v;
            }
        }
    }
}

__global__ __launch_bounds__(RC) void reduce_kernel()
{
    int b = blockIdx.x, c = threadIdx.x;
    float s = 0.f;
    const float* base = g_H + (size_t)b*RK*RC + c;
    #pragma unroll 10
    for (int k = 0; k < RK; k++) s += base[k*RC];
    g_S[b*RC + c] = s;
}

__global__ __launch_bounds__(RC) void gemm2_kernel(
    const float* __restrict__ W2, const float* __restrict__ b2,
    const float* __restrict__ fb_sum, float* __restrict__ out_sum)
{
    int b = blockIdx.x, c = threadIdx.x;
    __shared__ float sr[RC];
    sr[c] = g_S[b*RC + c];
    __syncthreads();
    float a = b2[c];
    #pragma unroll 8
    for (int d = 0; d < RC; d++)
        a = fmaf(sr[d], W2[d*RC + c], a);
    out_sum[b*RC + c] = g_used[b] ? a : fb_sum[c];
}

// ---------------- launch ----------------
extern "C" void kernel_launch(void* const* d_in, const int* in_sizes, int n_in,
                              void* d_out, int out_size)
{
    const float* current_repr = (const float*)d_in[0];
    const int*   session_ids  = (const int*)  d_in[1];
    const float* item_emb     = (const float*)d_in[2];
    const float* feature_q    = (const float*)d_in[3];
    const int*   session_q    = (const int*)  d_in[4];
    const int*   target_q     = (const int*)  d_in[5];
    const float* Wq = (const float*)d_in[6];
    const float* bq = (const float*)d_in[7];
    const float* Wk = (const float*)d_in[8];
    const float* bk = (const float*)d_in[9];
    const float* W1 = (const float*)d_in[10];
    const float* b1 = (const float*)d_in[11];
    const float* W2 = (const float*)d_in[12];
    const float* b2 = (const float*)d_in[13];
    const float* fb_ctx = (const float*)d_in[14];
    const float* fb_sum = (const float*)d_in[15];

    float* out = (float*)d_out;
    float* out_ctx  = out;
    float* out_sum  = out + (size_t)RB*RD;
    float* out_used = out + (size_t)RB*RD + (size_t)RB*RC;

    float *d_qn, *d_kn;
    __nv_bfloat16 *d_qh, *d_kh;
    cudaGetSymbolAddress((void**)&d_qn, g_qn);
    cudaGetSymbolAddress((void**)&d_kn, g_kn);
    cudaGetSymbolAddress((void**)&d_qh, g_qh);
    cudaGetSymbolAddress((void**)&d_kh, g_kh);

    // launch index 3 is the ncu capture slot -> proj_k (vectorized) this round
    sess_pad_kernel<<<(RMP+255)/256, 256>>>(session_q);
    w1split_kernel<<<(RC*RC+255)/256, 256>>>(W1);
    proj_kernel<<<RB/KP_ROWS, 128>>>(current_repr, Wq, bq, d_qn, d_qh);
    proj_kernel<<<RM/KP_ROWS, 128>>>(feature_q, Wk, bk, d_kn, d_kh);
    dim3 sg(RMP/128, RB/128);
    sims_mma_kernel<<<sg, 256>>>(session_ids);
    topk_kernel<<<RB*TSEG, TK_TPB>>>();
    refine_kernel<<<RB, NKT>>>();
    attn_ctx_kernel<<<RB, RD>>>(feature_q, target_q, fb_ctx, out_ctx, out_used);
    dim3 g1(RC/128, RNR/128);
    gemm1_mma_kernel<<<g1, 256>>>(feature_q, item_emb, b1);
    reduce_kernel<<<RB, RC>>>();
    gemm2_kernel<<<RB, RC>>>(W2, b2, fb_sum, out_sum);
}

// round 14
// speedup vs baseline: 1.8033x; 1.8033x over previous
#include <cuda_runtime.h>
#include <cuda_bf16.h>
#include <cstdint>
#include <math.h>

#define RB   1024
#define RD   128
#define RC   256
#define RM   100000
#define RMP  100096          // M padded to 128
#define RK   50
#define NK   64              // candidates per segment
#define TSEG 4               // segments per row
#define SEGLEN (RM/TSEG)     // 25000 (multiple of 8)
#define NKT  (NK*TSEG)       // 256 candidates per row total
#define RNR  (RB*RK)         // 51200
#define KE1  768             // 3-term split K for gemm1
#define INV_T 14.285714285714286f

// ---------------- device scratch ----------------
__device__ __align__(256) float g_qn[RB*RD];
__device__ __align__(256) float g_kn[(size_t)RMP*RD];   // zero-init
__device__ __align__(256) __nv_bfloat16 g_qh[RB*RD];
__device__ __align__(256) __nv_bfloat16 g_kh[(size_t)RMP*RD];  // padded rows stay 0
__device__ __align__(256) __nv_bfloat16 g_w1t[(size_t)RC*KE1]; // [c][k] split: hi,lo,hi
__device__ __align__(256) int   g_sess[RMP];
__device__ __align__(256) __nv_bfloat16 g_simsb[(size_t)RB*RMP];
__device__ __align__(256) int   g_candi[RB*NKT];
__device__ __align__(256) float g_topv[RB*RK];
__device__ __align__(256) int   g_topi[RB*RK];
__device__ __align__(256) float g_w[RNR];
__device__ __align__(256) int   g_tgt[RNR];
__device__ __align__(256) int   g_ixs[RNR];
__device__ __align__(256) int   g_used[RB];
__device__ __align__(256) float g_H[(size_t)RNR*RC];
__device__ __align__(256) float g_S[RB*RC];

#define SPAD 40     // bf16 per smem row (32 data + 8 pad)

// ---------------- SIMT projection + l2norm, exact fp32 (order-preserving vectorized) ----------------
#define KP_ROWS 32
__global__ __launch_bounds__(128) void proj_kernel(
    const float* __restrict__ X, const float* __restrict__ W,
    const float* __restrict__ bias, float* __restrict__ out,
    __nv_bfloat16* __restrict__ out_bf)
{
    __shared__ float xs[KP_ROWS][RD];
    __shared__ float os[KP_ROWS][RD+1];
    __shared__ float n4[KP_ROWS][4];
    int tid = threadIdx.x;
    size_t base = (size_t)blockIdx.x * KP_ROWS;
    #pragma unroll
    for (int rr = 0; rr < KP_ROWS; rr++)
        xs[rr][tid] = X[(base+rr)*RD + tid];
    __syncthreads();
    float acc[KP_ROWS];
    float bv = bias[tid];
    #pragma unroll
    for (int rr = 0; rr < KP_ROWS; rr++) acc[rr] = bv;
    // identical fmaf chain order (ascending d) — LDS vectorized only
    for (int d = 0; d < RD; d += 4){
        float w0 = W[(d+0)*RD + tid];
        float w1 = W[(d+1)*RD + tid];
        float w2 = W[(d+2)*RD + tid];
        float w3 = W[(d+3)*RD + tid];
        #pragma unroll
        for (int rr = 0; rr < KP_ROWS; rr++){
            float4 xv = *(const float4*)&xs[rr][d];
            float a = acc[rr];
            a = fmaf(xv.x, w0, a);
            a = fmaf(xv.y, w1, a);
            a = fmaf(xv.z, w2, a);
            a = fmaf(xv.w, w3, a);
            acc[rr] = a;
        }
    }
    #pragma unroll
    for (int rr = 0; rr < KP_ROWS; rr++) os[rr][tid] = acc[rr];
    __syncthreads();
    {
        int rr = tid >> 2, q = tid & 3;
        float s = 0.f;
        #pragma unroll
        for (int j = 0; j < 32; j++){ float v = os[rr][q*32 + j]; s = fmaf(v, v, s); }
        n4[rr][q] = s;
    }
    __syncthreads();
    if (tid < KP_ROWS){
        float t = n4[tid][0] + n4[tid][1] + n4[tid][2] + n4[tid][3];
        n4[tid][0] = 1.0f / fmaxf(sqrtf(t), 1e-12f);
    }
    __syncthreads();
    #pragma unroll
    for (int rr = 0; rr < KP_ROWS; rr++){
        float v = os[rr][tid] * n4[rr][0];
        out[(base+rr)*RD + tid] = v;
        out_bf[(base+rr)*RD + tid] = __float2bfloat16(v);
    }
}

__global__ void sess_pad_kernel(const int* __restrict__ sq){
    int i = blockIdx.x*256 + threadIdx.x;
    if (i < RMP) g_sess[i] = (i < RM) ? sq[i] : -1;
}

// ---------------- W1 3-term split, transposed to [c][k]: chunks hi, lo, hi ----------------
__global__ __launch_bounds__(256) void w1split_kernel(const float* __restrict__ W1){
    int idx = blockIdx.x*256 + threadIdx.x;   // k*256 + c
    if (idx >= RC*RC) return;
    int k = idx >> 8, c = idx & 255;
    float x = W1[idx];
    __nv_bfloat16 hi = __float2bfloat16(x);
    __nv_bfloat16 lo = __float2bfloat16(x - __bfloat162float(hi));
    size_t b = (size_t)c*KE1 + k;
    g_w1t[b] = hi; g_w1t[b+256] = lo; g_w1t[b+512] = hi;
}

// ---------------- sims = qh @ kh^T via bf16 mma, K=128; bf16 output, staged stores ----------------
__global__ __launch_bounds__(256) void sims_mma_kernel(const int* __restrict__ sessid)
{
    __shared__ __nv_bfloat16 sAB[2*128*SPAD];
    __nv_bfloat16 (*As)[SPAD] = (__nv_bfloat16(*)[SPAD])sAB;
    __nv_bfloat16 (*Bs)[SPAD] = (__nv_bfloat16(*)[SPAD])(sAB + 128*SPAD);
    __shared__ int sids[128];
    __shared__ int msess[128];

    int tid  = threadIdx.x;
    int lane = tid & 31;
    int wid  = tid >> 5;
    int wm   = wid >> 2;
    int wn   = wid & 3;
    int m0 = blockIdx.x * 128;
    int b0 = blockIdx.y * 128;

    if (tid < 128){ sids[tid] = sessid[b0 + tid]; msess[tid] = g_sess[m0 + tid]; }

    float acc[4][4][4];
    #pragma unroll
    for (int i = 0; i < 4; i++)
        #pragma unroll
        for (int j = 0; j < 4; j++)
            #pragma unroll
            for (int r = 0; r < 4; r++) acc[i][j][r] = 0.f;

    const __nv_bfloat16* qbase = g_qh + (size_t)b0*RD;
    const __nv_bfloat16* kbase = g_kh + (size_t)m0*RD;
    int s0 = tid, s1 = tid + 256;
    int ra0 = s0 >> 2, ca0 = (s0 & 3) * 8;
    int ra1 = s1 >> 2, ca1 = (s1 & 3) * 8;

    uint4 pa0 = *(const uint4*)(qbase + (size_t)ra0*RD + ca0);
    uint4 pa1 = *(const uint4*)(qbase + (size_t)ra1*RD + ca1);
    uint4 pb0 = *(const uint4*)(kbase + (size_t)ra0*RD + ca0);
    uint4 pb1 = *(const uint4*)(kbase + (size_t)ra1*RD + ca1);

    for (int kc = 0; kc < RD; kc += 32){
        __syncthreads();
        *(uint4*)&As[ra0][ca0] = pa0;
        *(uint4*)&As[ra1][ca1] = pa1;
        *(uint4*)&Bs[ra0][ca0] = pb0;
        *(uint4*)&Bs[ra1][ca1] = pb1;
        __syncthreads();
        int kn = kc + 32;
        if (kn < RD){
            pa0 = *(const uint4*)(qbase + (size_t)ra0*RD + kn + ca0);
            pa1 = *(const uint4*)(qbase + (size_t)ra1*RD + kn + ca1);
            pb0 = *(const uint4*)(kbase + (size_t)ra0*RD + kn + ca0);
            pb1 = *(const uint4*)(kbase + (size_t)ra1*RD + kn + ca1);
        }
        #pragma unroll
        for (int ks = 0; ks < 2; ks++){
            int kk = ks * 16;
            uint32_t af[4][4], bf[4][2];
            #pragma unroll
            for (int mi = 0; mi < 4; mi++){
                uint32_t addr = (uint32_t)__cvta_generic_to_shared(
                    &As[wm*64 + mi*16 + (lane & 15)][kk + (lane >> 4)*8]);
                asm volatile("ldmatrix.sync.aligned.m8n8.x4.shared.b16 {%0,%1,%2,%3}, [%4];"
                    : "=r"(af[mi][0]), "=r"(af[mi][1]), "=r"(af[mi][2]), "=r"(af[mi][3])
                    : "r"(addr));
            }
            #pragma unroll
            for (int ni = 0; ni < 4; ni++){
                uint32_t addr = (uint32_t)__cvta_generic_to_shared(
                    &Bs[wn*32 + ni*8 + (lane & 7)][kk + ((lane >> 3) & 1)*8]);
                asm volatile("ldmatrix.sync.aligned.m8n8.x2.shared.b16 {%0,%1}, [%2];"
                    : "=r"(bf[ni][0]), "=r"(bf[ni][1]) : "r"(addr));
            }
            #pragma unroll
            for (int mi = 0; mi < 4; mi++)
                #pragma unroll
                for (int ni = 0; ni < 4; ni++){
                    asm volatile(
                        "mma.sync.aligned.m16n8k16.row.col.f32.bf16.bf16.f32 "
                        "{%0,%1,%2,%3}, {%4,%5,%6,%7}, {%8,%9}, {%0,%1,%2,%3};"
                        : "+f"(acc[mi][ni][0]), "+f"(acc[mi][ni][1]),
                          "+f"(acc[mi][ni][2]), "+f"(acc[mi][ni][3])
                        : "r"(af[mi][0]), "r"(af[mi][1]), "r"(af[mi][2]), "r"(af[mi][3]),
                          "r"(bf[ni][0]), "r"(bf[ni][1]));
                }
        }
    }

    // epilogue: mask + stage 64-row halves in smem, then coalesced 16B stores
    const unsigned short NEGINF = 0xFF80;
    __nv_bfloat16* stg = sAB;     // [64][136]
    #pragma unroll
    for (int p = 0; p < 2; p++){
        __syncthreads();
        if (wm == p){
            #pragma unroll
            for (int mi = 0; mi < 4; mi++){
                #pragma unroll
                for (int h = 0; h < 2; h++){
                    int lr = mi*16 + (lane >> 2) + h*8;      // 0..63
                    int sid = sids[p*64 + lr];
                    #pragma unroll
                    for (int ni = 0; ni < 4; ni++){
                        int cl = wn*32 + ni*8 + (lane & 3)*2;
                        __nv_bfloat162 hv = __float22bfloat162_rn(
                            make_float2(acc[mi][ni][h*2+0], acc[mi][ni][h*2+1]));
                        unsigned int u = *(unsigned int*)&hv;
                        if (msess[cl]   == sid) u = (u & 0xFFFF0000u) | NEGINF;
                        if (msess[cl+1] == sid) u = (u & 0x0000FFFFu) | ((unsigned)NEGINF << 16);
                        *(unsigned int*)&stg[lr*136 + cl] = u;
                    }
                }
            }
        }
        __syncthreads();
        int lrow = tid >> 2, t4 = tid & 3;
        #pragma unroll
        for (int i = 0; i < 4; i++){
            int seg = t4*4 + i;                              // 0..15, 8 bf16 each
            uint4 v = *(uint4*)&stg[lrow*136 + seg*8];
            *(uint4*)&g_simsb[(size_t)(b0 + p*64 + lrow)*RMP + m0 + seg*8] = v;
        }
    }
}

// ---------------- streaming top-NK per row segment over bf16 sims ----------------
#define TK_CAP 3072
#define TK_TPB 256

__device__ __forceinline__ bool better(float v, int m, float bv, int bm){
    return (v > bv) || (v == bv && m < bm);
}

__device__ void topk_flush(float* sval, int* sidx, int* cnt, float* thr,
                           float* selv, int* seli, float* wv, int* wm, int* wp, int tid)
{
    int n = *cnt; if (n > TK_CAP) n = TK_CAP;
    __syncthreads();
    for (int r = 0; r < NK; r++){
        float bv = -INFINITY; int bm = 0x7fffffff; int bp = -1;
        for (int i = tid; i < n; i += TK_TPB){
            float v = sval[i]; int m = sidx[i];
            if (v > -3.0e38f && better(v, m, bv, bm)){ bv = v; bm = m; bp = i; }
        }
        #pragma unroll
        for (int o = 16; o > 0; o >>= 1){
            float ov = __shfl_down_sync(0xffffffffu, bv, o);
            int   om = __shfl_down_sync(0xffffffffu, bm, o);
            int   op = __shfl_down_sync(0xffffffffu, bp, o);
            if (op >= 0 && (bp < 0 || better(ov, om, bv, bm))){ bv = ov; bm = om; bp = op; }
        }
        if ((tid & 31) == 0){ wv[tid >> 5] = bv; wm[tid >> 5] = bm; wp[tid >> 5] = bp; }
        __syncthreads();
        if (tid == 0){
            float v2 = wv[0]; int m2 = wm[0]; int p2 = wp[0];
            #pragma unroll
            for (int q = 1; q < 8; q++)
                if (wp[q] >= 0 && (p2 < 0 || better(wv[q], wm[q], v2, m2))){ v2 = wv[q]; m2 = wm[q]; p2 = wp[q]; }
            selv[r] = (p2 >= 0) ? v2 : -INFINITY;
            seli[r] = (p2 >= 0) ? m2 : -1;
            if (p2 >= 0) sval[p2] = -INFINITY;
        }
        __syncthreads();
    }
    if (tid < NK){ sval[tid] = selv[tid]; sidx[tid] = (seli[tid] >= 0) ? seli[tid] : 0x7ffffffe; }
    if (tid == 0){ *cnt = NK; *thr = selv[NK-1]; }
    __syncthreads();
}

__global__ __launch_bounds__(TK_TPB) void topk_kernel()
{
    int blk = blockIdx.x;
    int b   = blk / TSEG;
    int seg = blk % TSEG;
    int tid = threadIdx.x;
    __shared__ float sval[TK_CAP];
    __shared__ int   sidx[TK_CAP];
    __shared__ float selv[NK];
    __shared__ int   seli[NK];
    __shared__ float wv[8];
    __shared__ int   wm[8];
    __shared__ int   wp[8];
    __shared__ int   cnt;
    __shared__ float thr;
    if (tid == 0){ cnt = 0; thr = -INFINITY; }
    __syncthreads();
    int sbase = seg * SEGLEN;
    const __nv_bfloat16* row = g_simsb + (size_t)b * RMP + sbase;
    for (int base = 0; base < SEGLEN; base += 2048){
        int i = base + tid*8;
        float t = thr;
        if (i < SEGLEN){  // SEGLEN % 8 == 0
            uint4 pk = *(const uint4*)(row + i);
            unsigned int us[4] = {pk.x, pk.y, pk.z, pk.w};
            #pragma unroll
            for (int q = 0; q < 4; q++){
                __nv_bfloat162 h2 = *(__nv_bfloat162*)&us[q];
                float2 fv = __bfloat1622float2(h2);
                if (fv.x >= t && fv.x > -3.0e38f){ int p = atomicAdd(&cnt,1); if (p < TK_CAP){ sval[p]=fv.x; sidx[p]=sbase+i+q*2;   } }
                if (fv.y >= t && fv.y > -3.0e38f){ int p = atomicAdd(&cnt,1); if (p < TK_CAP){ sval[p]=fv.y; sidx[p]=sbase+i+q*2+1; } }
            }
        }
        __syncthreads();
        if (cnt > TK_CAP - 2048)
            topk_flush(sval, sidx, &cnt, &thr, selv, seli, wv, wm, wp, tid);
        __syncthreads();
    }
    topk_flush(sval, sidx, &cnt, &thr, selv, seli, wv, wm, wp, tid);
    if (tid < NK)
        g_candi[(b*TSEG + seg)*NK + tid] = seli[tid];
}

// ---------------- compensated-fp32 refinement of the NKT candidates + exact top-50 ----------------
__global__ __launch_bounds__(NKT) void refine_kernel()
{
    int b = blockIdx.x, k = threadIdx.x;
    __shared__ float q[RD];
    __shared__ float rv[NKT];
    __shared__ int   ri[NKT];
    for (int t = k; t < RD; t += NKT) q[t] = g_qn[b*RD + t];
    __syncthreads();
    int idx = g_candi[b*NKT + k];
    float fv = -INFINITY;
    if (idx >= 0){
        const float* kr = &g_kn[(size_t)idx*RD];
        // double-float (compensated) dot: error ~ n*2^-48, rounds same as fp64 path
        float sh = 0.f, sl = 0.f;
        #pragma unroll 4
        for (int d = 0; d < RD; d++){
            float a = q[d], w = kr[d];
            float p  = a * w;
            float pe = fmaf(a, w, -p);          // exact product tail
            float t  = sh + p;                   // TwoSum
            float z  = t - sh;
            float e  = (sh - (t - z)) + (p - z);
            sh = t;
            sl += e + pe;
        }
        fv = sh + sl;
    }
    rv[k] = fv;
    ri[k] = (idx >= 0) ? idx : (0x40000000 + k);   // unique sentinel per slot
    __syncthreads();
    float mv = rv[k]; int mi = ri[k];
    int rank = 0;
    for (int j = 0; j < NKT; j++){
        float v = rv[j]; int m = ri[j];
        rank += ((v > mv) || (v == mv && m < mi)) ? 1 : 0;
    }
    if (rank < RK){
        g_topv[b*RK + rank] = mv;
        g_topi[b*RK + rank] = (mi >= 0x40000000) ? -1 : mi;
    }
}

// ---------------- softmax attn + context + gather metadata ----------------
__global__ __launch_bounds__(RD) void attn_ctx_kernel(
    const float* __restrict__ fq, const int* __restrict__ tq,
    const float* __restrict__ fb_ctx, float* __restrict__ out_ctx,
    float* __restrict__ out_used)
{
    int b = blockIdx.x, tid = threadIdx.x;
    __shared__ float v[RK];
    __shared__ int   ixs[RK];
    __shared__ float w[RK];
    __shared__ int   uflag;
    if (tid < RK){ v[tid] = g_topv[b*RK + tid]; int id = g_topi[b*RK + tid]; ixs[tid] = (id >= 0) ? id : 0;
                   g_ixs[b*RK + tid] = ixs[tid];
                   g_tgt[b*RK + tid] = (id >= 0) ? max(tq[ixs[tid]], 0) : 0; }
    __syncthreads();
    if (tid == 0){
        float mx = -INFINITY; int u = 0;
        for (int k = 0; k < RK; k++){
            float vk = v[k];
            if (vk > -1e30f){ u = 1; if (vk > mx) mx = vk; }
        }
        float s = 0.f;
        for (int k = 0; k < RK; k++){
            float vk = v[k];
            float wk = (vk > -1e30f) ? expf((vk - mx) * INV_T) : 0.f;
            w[k] = wk; s += wk;
        }
        float inv = 1.0f / fmaxf(s, 1e-12f);
        for (int k = 0; k < RK; k++) w[k] *= inv;
        uflag = u;
        g_used[b] = u;
        out_used[b] = u ? 1.0f : 0.0f;
    }
    __syncthreads();
    if (tid < RK) g_w[b*RK + tid] = w[tid];
    float c = 0.f;
    for (int k = 0; k < RK; k++){
        float wk = w[k];
        if (wk != 0.f) c = fmaf(wk, fq[(size_t)ixs[k]*RD + tid], c);
    }
    out_ctx[b*RD + tid] = uflag ? c : fb_ctx[tid];
}

// ---------------- gemm1 via bf16 mma, 3-term split (K=768) ----------------
__device__ __forceinline__ uint4 lda8_split(
    const float* __restrict__ fq, const float* __restrict__ item_emb,
    int rowf, int rowt, int kg)   // kg = global col in [0, KE1)
{
    int t = kg >> 8, sc = kg & 255;
    const float* src = (sc < 128) ? (fq + (size_t)rowf*RD + sc)
                                  : (item_emb + (size_t)rowt*RD + (sc - 128));
    float4 u = *(const float4*)src;
    float4 v = *(const float4*)(src + 4);
    float xs[8] = {u.x,u.y,u.z,u.w,v.x,v.y,v.z,v.w};
    bool lo = (t == 2);
    uint4 r; unsigned short* p = (unsigned short*)&r;
    #pragma unroll
    for (int i = 0; i < 8; i++){
        __nv_bfloat16 hi = __float2bfloat16(xs[i]);
        p[i] = lo ? __bfloat16_as_ushort(__float2bfloat16(xs[i] - __bfloat162float(hi)))
                  : __bfloat16_as_ushort(hi);
    }
    return r;
}

__global__ __launch_bounds__(256) void gemm1_mma_kernel(
    const float* __restrict__ fq, const float* __restrict__ item_emb,
    const float* __restrict__ b1)
{
    __shared__ __nv_bfloat16 As[128][SPAD];
    __shared__ __nv_bfloat16 Bs[128][SPAD];
    __shared__ int   rid[128];
    __shared__ int   tgd[128];
    __shared__ float wrow[128];

    int tid  = threadIdx.x;
    int lane = tid & 31;
    int wid  = tid >> 5;
    int wm   = wid >> 2;
    int wn   = wid & 3;
    int c0  = blockIdx.x * 128;
    int nr0 = blockIdx.y * 128;

    if (tid < 128){
        rid[tid]  = g_ixs[nr0 + tid];
        tgd[tid]  = g_tgt[nr0 + tid];
        wrow[tid] = g_w[nr0 + tid];
    }
    __syncthreads();

    float acc[4][4][4];
    #pragma unroll
    for (int i = 0; i < 4; i++)
        #pragma unroll
        for (int j = 0; j < 4; j++)
            #pragma unroll
            for (int r = 0; r < 4; r++) acc[i][j][r] = 0.f;

    int s0 = tid, s1 = tid + 256;
    int ra0 = s0 >> 2, ca0 = (s0 & 3) * 8;
    int ra1 = s1 >> 2, ca1 = (s1 & 3) * 8;
    const __nv_bfloat16* wbase = g_w1t + (size_t)c0*KE1;

    uint4 pa0 = lda8_split(fq, item_emb, rid[ra0], tgd[ra0], ca0);
    uint4 pa1 = lda8_split(fq, item_emb, rid[ra1], tgd[ra1], ca1);
    uint4 pb0 = *(const uint4*)(wbase + (size_t)ra0*KE1 + ca0);
    uint4 pb1 = *(const uint4*)(wbase + (size_t)ra1*KE1 + ca1);

    for (int kc = 0; kc < KE1; kc += 32){
        __syncthreads();
        *(uint4*)&As[ra0][ca0] = pa0;
        *(uint4*)&As[ra1][ca1] = pa1;
        *(uint4*)&Bs[ra0][ca0] = pb0;
        *(uint4*)&Bs[ra1][ca1] = pb1;
        __syncthreads();
        int kn = kc + 32;
        if (kn < KE1){
            pa0 = lda8_split(fq, item_emb, rid[ra0], tgd[ra0], kn + ca0);
            pa1 = lda8_split(fq, item_emb, rid[ra1], tgd[ra1], kn + ca1);
            pb0 = *(const uint4*)(wbase + (size_t)ra0*KE1 + kn + ca0);
            pb1 = *(const uint4*)(wbase + (size_t)ra1*KE1 + kn + ca1);
        }
        #pragma unroll
        for (int ks = 0; ks < 2; ks++){
            int kk = ks * 16;
            uint32_t af[4][4], bf[4][2];
            #pragma unroll
            for (int mi = 0; mi < 4; mi++){
                uint32_t addr = (uint32_t)__cvta_generic_to_shared(
                    &As[wm*64 + mi*16 + (lane & 15)][kk + (lane >> 4)*8]);
                asm volatile("ldmatrix.sync.aligned.m8n8.x4.shared.b16 {%0,%1,%2,%3}, [%4];"
                    : "=r"(af[mi][0]), "=r"(af[mi][1]), "=r"(af[mi][2]), "=r"(af[mi][3])
                    : "r"(addr));
            }
            #pragma unroll
            for (int ni = 0; ni < 4; ni++){
                uint32_t addr = (uint32_t)__cvta_generic_to_shared(
                    &Bs[wn*32 + ni*8 + (lane & 7)][kk + ((lane >> 3) & 1)*8]);
                asm volatile("ldmatrix.sync.aligned.m8n8.x2.shared.b16 {%0,%1}, [%2];"
                    : "=r"(bf[ni][0]), "=r"(bf[ni][1]) : "r"(addr));
            }
            #pragma unroll
            for (int mi = 0; mi < 4; mi++)
                #pragma unroll
                for (int ni = 0; ni < 4; ni++){
                    asm volatile(
                        "mma.sync.aligned.m16n8k16.row.col.f32.bf16.bf16.f32 "
                        "{%0,%1,%2,%3}, {%4,%5,%6,%7}, {%8,%9}, {%0,%1,%2,%3};"
                        : "+f"(acc[mi][ni][0]), "+f"(acc[mi][ni][1]),
                          "+f"(acc[mi][ni][2]), "+f"(acc[mi][ni][3])
                        : "r"(af[mi][0]), "r"(af[mi][1]), "r"(af[mi][2]), "r"(af[mi][3]),
                          "r"(bf[ni][0]), "r"(bf[ni][1]));
                }
        }
    }

    #pragma unroll
    for (int mi = 0; mi < 4; mi++){
        int rl0 = wm*64 + mi*16 + (lane >> 2);
        #pragma unroll
        for (int ni = 0; ni < 4; ni++){
            int cl = wn*32 + ni*8 + (lane & 3)*2;
            int c = c0 + cl;
            float bb0 = b1[c], bb1 = b1[c+1];
            #pragma unroll
            for (int h = 0; h < 2; h++){
                int rr = rl0 + h*8;
                float x0 = acc[mi][ni][h*2+0] + bb0;
                float x1 = acc[mi][ni][h*2+1] + bb1;
                float g0 = 0.5f * x0 * (1.0f + erff(x0 * 0.70710678118654752f));
                float g1 = 0.5f * x1 * (1.0f + erff(x1 * 0.70710678118654752f));
                float wk = wrow[rr];
                float2 v; v.x = wk * g0; v.y = wk * g1;
                *(float2*)&g_H[(size_t)(nr0 + rr)*RC + c] = v;
            }
        }
    }
}

__global__ __launch_bounds__(RC) void reduce_kernel()
{
    int b = blockIdx.x, c = threadIdx.x;
    float s = 0.f;
    const float* base = g_H + (size_t)b*RK*RC + c;
    #pragma unroll 10
    for (int k = 0; k < RK; k++) s += base[k*RC];
    g_S[b*RC + c] = s;
}

__global__ __launch_bounds__(RC) void gemm2_kernel(
    const float* __restrict__ W2, const float* __restrict__ b2,
    const float* __restrict__ fb_sum, float* __restrict__ out_sum)
{
    int b = blockIdx.x, c = threadIdx.x;
    __shared__ float sr[RC];
    sr[c] = g_S[b*RC + c];
    __syncthreads();
    float a = b2[c];
    #pragma unroll 8
    for (int d = 0; d < RC; d++)
        a = fmaf(sr[d], W2[d*RC + c], a);
    out_sum[b*RC + c] = g_used[b] ? a : fb_sum[c];
}

// ---------------- launch ----------------
extern "C" void kernel_launch(void* const* d_in, const int* in_sizes, int n_in,
                              void* d_out, int out_size)
{
    const float* current_repr = (const float*)d_in[0];
    const int*   session_ids  = (const int*)  d_in[1];
    const float* item_emb     = (const float*)d_in[2];
    const float* feature_q    = (const float*)d_in[3];
    const int*   session_q    = (const int*)  d_in[4];
    const int*   target_q     = (const int*)  d_in[5];
    const float* Wq = (const float*)d_in[6];
    const float* bq = (const float*)d_in[7];
    const float* Wk = (const float*)d_in[8];
    const float* bk = (const float*)d_in[9];
    const float* W1 = (const float*)d_in[10];
    const float* b1 = (const float*)d_in[11];
    const float* W2 = (const float*)d_in[12];
    const float* b2 = (const float*)d_in[13];
    const float* fb_ctx = (const float*)d_in[14];
    const float* fb_sum = (const float*)d_in[15];

    float* out = (float*)d_out;
    float* out_ctx  = out;
    float* out_sum  = out + (size_t)RB*RD;
    float* out_used = out + (size_t)RB*RD + (size_t)RB*RC;

    float *d_qn, *d_kn;
    __nv_bfloat16 *d_qh, *d_kh;
    cudaGetSymbolAddress((void**)&d_qn, g_qn);
    cudaGetSymbolAddress((void**)&d_kn, g_kn);
    cudaGetSymbolAddress((void**)&d_qh, g_qh);
    cudaGetSymbolAddress((void**)&d_kh, g_kh);

    sess_pad_kernel<<<(RMP+255)/256, 256>>>(session_q);
    w1split_kernel<<<(RC*RC+255)/256, 256>>>(W1);
    proj_kernel<<<RB/KP_ROWS, 128>>>(current_repr, Wq, bq, d_qn, d_qh);
    proj_kernel<<<RM/KP_ROWS, 128>>>(feature_q, Wk, bk, d_kn, d_kh);
    dim3 sg(RMP/128, RB/128);
    sims_mma_kernel<<<sg, 256>>>(session_ids);
    topk_kernel<<<RB*TSEG, TK_TPB>>>();
    refine_kernel<<<RB, NKT>>>();
    attn_ctx_kernel<<<RB, RD>>>(feature_q, target_q, fb_ctx, out_ctx, out_used);
    dim3 g1(RC/128, RNR/128);
    gemm1_mma_kernel<<<g1, 256>>>(feature_q, item_emb, b1);
    reduce_kernel<<<RB, RC>>>();
    gemm2_kernel<<<RB, RC>>>(W2, b2, fb_sum, out_sum);
}

// round 16
// speedup vs baseline: 4.2329x; 2.3474x over previous
#include <cuda_runtime.h>
#include <cuda_bf16.h>
#include <cstdint>
#include <math.h>

#define RB   1024
#define RD   128
#define RC   256
#define RM   100000
#define RMP  100096          // M padded to 128
#define RK   50
#define RNR  (RB*RK)         // 51200
#define KE1  768             // 3-term split K for gemm1
#define HBINS 4096
#define CAND_MAX 2048
#define INV_T 14.285714285714286f

// ---------------- device scratch ----------------
__device__ __align__(256) float g_qn[RB*RD];
__device__ __align__(256) float g_kn[(size_t)RMP*RD];   // zero-init
__device__ __align__(256) __nv_bfloat16 g_qh[RB*RD];
__device__ __align__(256) __nv_bfloat16 g_kh[(size_t)RMP*RD];  // padded rows stay 0
__device__ __align__(256) __nv_bfloat16 g_w1t[(size_t)RC*KE1]; // [c][k] split: hi,lo,hi
__device__ __align__(256) __nv_bfloat16 g_simsb[(size_t)RB*RMP];
__device__ __align__(256) int   g_candi[(size_t)RB*CAND_MAX];
__device__ __align__(256) int   g_ccnt[RB];
__device__ __align__(256) float g_topv[RB*RK];
__device__ __align__(256) int   g_topi[RB*RK];
__device__ __align__(256) float g_w[RNR];
__device__ __align__(256) int   g_tgt[RNR];
__device__ __align__(256) int   g_ixs[RNR];
__device__ __align__(256) int   g_used[RB];
__device__ __align__(256) float g_H[(size_t)RNR*RC];
__device__ __align__(256) float g_S[RB*RC];

#define SPAD 40     // bf16 per smem row (32 data + 8 pad)

// ---------------- SIMT projection + l2norm, exact fp32 (order-preserving vectorized) ----------------
#define KP_ROWS 32
__global__ __launch_bounds__(128) void proj_kernel(
    const float* __restrict__ X, const float* __restrict__ W,
    const float* __restrict__ bias, float* __restrict__ out,
    __nv_bfloat16* __restrict__ out_bf)
{
    __shared__ float xs[KP_ROWS][RD];
    __shared__ float os[KP_ROWS][RD+1];
    __shared__ float n4[KP_ROWS][4];
    int tid = threadIdx.x;
    size_t base = (size_t)blockIdx.x * KP_ROWS;
    #pragma unroll
    for (int rr = 0; rr < KP_ROWS; rr++)
        xs[rr][tid] = X[(base+rr)*RD + tid];
    __syncthreads();
    float acc[KP_ROWS];
    float bv = bias[tid];
    #pragma unroll
    for (int rr = 0; rr < KP_ROWS; rr++) acc[rr] = bv;
    for (int d = 0; d < RD; d += 4){
        float w0 = W[(d+0)*RD + tid];
        float w1 = W[(d+1)*RD + tid];
        float w2 = W[(d+2)*RD + tid];
        float w3 = W[(d+3)*RD + tid];
        #pragma unroll
        for (int rr = 0; rr < KP_ROWS; rr++){
            float4 xv = *(const float4*)&xs[rr][d];
            float a = acc[rr];
            a = fmaf(xv.x, w0, a);
            a = fmaf(xv.y, w1, a);
            a = fmaf(xv.z, w2, a);
            a = fmaf(xv.w, w3, a);
            acc[rr] = a;
        }
    }
    #pragma unroll
    for (int rr = 0; rr < KP_ROWS; rr++) os[rr][tid] = acc[rr];
    __syncthreads();
    {
        int rr = tid >> 2, q = tid & 3;
        float s = 0.f;
        #pragma unroll
        for (int j = 0; j < 32; j++){ float v = os[rr][q*32 + j]; s = fmaf(v, v, s); }
        n4[rr][q] = s;
    }
    __syncthreads();
    if (tid < KP_ROWS){
        float t = n4[tid][0] + n4[tid][1] + n4[tid][2] + n4[tid][3];
        n4[tid][0] = 1.0f / fmaxf(sqrtf(t), 1e-12f);
    }
    __syncthreads();
    #pragma unroll
    for (int rr = 0; rr < KP_ROWS; rr++){
        float v = os[rr][tid] * n4[rr][0];
        out[(base+rr)*RD + tid] = v;
        out_bf[(base+rr)*RD + tid] = __float2bfloat16(v);
    }
}

// ---------------- W1 3-term split, transposed to [c][k]: chunks hi, lo, hi ----------------
__global__ __launch_bounds__(256) void w1split_kernel(const float* __restrict__ W1){
    int idx = blockIdx.x*256 + threadIdx.x;   // k*256 + c
    if (idx >= RC*RC) return;
    int k = idx >> 8, c = idx & 255;
    float x = W1[idx];
    __nv_bfloat16 hi = __float2bfloat16(x);
    __nv_bfloat16 lo = __float2bfloat16(x - __bfloat162float(hi));
    size_t b = (size_t)c*KE1 + k;
    g_w1t[b] = hi; g_w1t[b+256] = lo; g_w1t[b+512] = hi;
}

// ---------------- sims = qh @ kh^T via bf16 mma, K=128; bf16 output, staged stores ----------------
__global__ __launch_bounds__(256) void sims_mma_kernel(
    const int* __restrict__ sessid, const int* __restrict__ sq)
{
    __shared__ __nv_bfloat16 sAB[2*128*SPAD];
    __nv_bfloat16 (*As)[SPAD] = (__nv_bfloat16(*)[SPAD])sAB;
    __nv_bfloat16 (*Bs)[SPAD] = (__nv_bfloat16(*)[SPAD])(sAB + 128*SPAD);
    __shared__ int sids[128];
    __shared__ int msess[128];

    int tid  = threadIdx.x;
    int lane = tid & 31;
    int wid  = tid >> 5;
    int wm   = wid >> 2;
    int wn   = wid & 3;
    int m0 = blockIdx.x * 128;
    int b0 = blockIdx.y * 128;

    if (tid < 128){
        sids[tid]  = sessid[b0 + tid];
        msess[tid] = (m0 + tid < RM) ? sq[m0 + tid] : -1;
    }

    float acc[4][4][4];
    #pragma unroll
    for (int i = 0; i < 4; i++)
        #pragma unroll
        for (int j = 0; j < 4; j++)
            #pragma unroll
            for (int r = 0; r < 4; r++) acc[i][j][r] = 0.f;

    const __nv_bfloat16* qbase = g_qh + (size_t)b0*RD;
    const __nv_bfloat16* kbase = g_kh + (size_t)m0*RD;
    int s0 = tid, s1 = tid + 256;
    int ra0 = s0 >> 2, ca0 = (s0 & 3) * 8;
    int ra1 = s1 >> 2, ca1 = (s1 & 3) * 8;

    uint4 pa0 = *(const uint4*)(qbase + (size_t)ra0*RD + ca0);
    uint4 pa1 = *(const uint4*)(qbase + (size_t)ra1*RD + ca1);
    uint4 pb0 = *(const uint4*)(kbase + (size_t)ra0*RD + ca0);
    uint4 pb1 = *(const uint4*)(kbase + (size_t)ra1*RD + ca1);

    for (int kc = 0; kc < RD; kc += 32){
        __syncthreads();
        *(uint4*)&As[ra0][ca0] = pa0;
        *(uint4*)&As[ra1][ca1] = pa1;
        *(uint4*)&Bs[ra0][ca0] = pb0;
        *(uint4*)&Bs[ra1][ca1] = pb1;
        __syncthreads();
        int kn = kc + 32;
        if (kn < RD){
            pa0 = *(const uint4*)(qbase + (size_t)ra0*RD + kn + ca0);
            pa1 = *(const uint4*)(qbase + (size_t)ra1*RD + kn + ca1);
            pb0 = *(const uint4*)(kbase + (size_t)ra0*RD + kn + ca0);
            pb1 = *(const uint4*)(kbase + (size_t)ra1*RD + kn + ca1);
        }
        #pragma unroll
        for (int ks = 0; ks < 2; ks++){
            int kk = ks * 16;
            uint32_t af[4][4], bf[4][2];
            #pragma unroll
            for (int mi = 0; mi < 4; mi++){
                uint32_t addr = (uint32_t)__cvta_generic_to_shared(
                    &As[wm*64 + mi*16 + (lane & 15)][kk + (lane >> 4)*8]);
                asm volatile("ldmatrix.sync.aligned.m8n8.x4.shared.b16 {%0,%1,%2,%3}, [%4];"
                    : "=r"(af[mi][0]), "=r"(af[mi][1]), "=r"(af[mi][2]), "=r"(af[mi][3])
                    : "r"(addr));
            }
            #pragma unroll
            for (int ni = 0; ni < 4; ni++){
                uint32_t addr = (uint32_t)__cvta_generic_to_shared(
                    &Bs[wn*32 + ni*8 + (lane & 7)][kk + ((lane >> 3) & 1)*8]);
                asm volatile("ldmatrix.sync.aligned.m8n8.x2.shared.b16 {%0,%1}, [%2];"
                    : "=r"(bf[ni][0]), "=r"(bf[ni][1]) : "r"(addr));
            }
            #pragma unroll
            for (int mi = 0; mi < 4; mi++)
                #pragma unroll
                for (int ni = 0; ni < 4; ni++){
                    asm volatile(
                        "mma.sync.aligned.m16n8k16.row.col.f32.bf16.bf16.f32 "
                        "{%0,%1,%2,%3}, {%4,%5,%6,%7}, {%8,%9}, {%0,%1,%2,%3};"
                        : "+f"(acc[mi][ni][0]), "+f"(acc[mi][ni][1]),
                          "+f"(acc[mi][ni][2]), "+f"(acc[mi][ni][3])
                        : "r"(af[mi][0]), "r"(af[mi][1]), "r"(af[mi][2]), "r"(af[mi][3]),
                          "r"(bf[ni][0]), "r"(bf[ni][1]));
                }
        }
    }

    // epilogue: mask + stage 64-row halves in smem, then coalesced 16B stores
    const unsigned short NEGINF = 0xFF80;
    __nv_bfloat16* stg = sAB;     // [64][136]
    #pragma unroll
    for (int p = 0; p < 2; p++){
        __syncthreads();
        if (wm == p){
            #pragma unroll
            for (int mi = 0; mi < 4; mi++){
                #pragma unroll
                for (int h = 0; h < 2; h++){
                    int lr = mi*16 + (lane >> 2) + h*8;      // 0..63
                    int sid = sids[p*64 + lr];
                    #pragma unroll
                    for (int ni = 0; ni < 4; ni++){
                        int cl = wn*32 + ni*8 + (lane & 3)*2;
                        __nv_bfloat162 hv = __float22bfloat162_rn(
                            make_float2(acc[mi][ni][h*2+0], acc[mi][ni][h*2+1]));
                        unsigned int u = *(unsigned int*)&hv;
                        if (msess[cl]   == sid) u = (u & 0xFFFF0000u) | NEGINF;
                        if (msess[cl+1] == sid) u = (u & 0x0000FFFFu) | ((unsigned)NEGINF << 16);
                        *(unsigned int*)&stg[lr*136 + cl] = u;
                    }
                }
            }
        }
        __syncthreads();
        int lrow = tid >> 2, t4 = tid & 3;
        #pragma unroll
        for (int i = 0; i < 4; i++){
            int seg = t4*4 + i;                              // 0..15, 8 bf16 each
            uint4 v = *(uint4*)&stg[lrow*136 + seg*8];
            *(uint4*)&g_simsb[(size_t)(b0 + p*64 + lrow)*RMP + m0 + seg*8] = v;
        }
    }
}

// ---------------- histogram-threshold candidate selection (no flushes) ----------------
__device__ __forceinline__ unsigned int bf16key(unsigned int h){
    return (h & 0x8000u) ? (0xFFFFu - h) : (h | 0x8000u);
}

__global__ __launch_bounds__(256) void topsel_kernel()
{
    int b = blockIdx.x, tid = threadIdx.x;
    __shared__ unsigned int bins[HBINS];
    __shared__ unsigned int chunk[256];
    __shared__ int s_thr;
    __shared__ int s_cnt;
    for (int i = tid; i < HBINS; i += 256) bins[i] = 0;
    if (tid == 0) s_cnt = 0;
    __syncthreads();
    const __nv_bfloat16* row = g_simsb + (size_t)b*RMP;
    for (int i = tid*8; i < RM; i += 2048){
        uint4 pk = *(const uint4*)(row + i);
        unsigned int us[4] = {pk.x, pk.y, pk.z, pk.w};
        #pragma unroll
        for (int q = 0; q < 4; q++){
            unsigned int u = us[q];
            unsigned int k0 = bf16key(u & 0xFFFFu);
            unsigned int k1 = bf16key(u >> 16);
            atomicAdd(&bins[k0 >> 4], 1u);
            atomicAdd(&bins[k1 >> 4], 1u);
        }
    }
    __syncthreads();
    unsigned int cs = 0;
    #pragma unroll
    for (int j = 0; j < 16; j++) cs += bins[tid*16 + j];
    chunk[tid] = cs;
    __syncthreads();
    if (tid == 0){
        unsigned int cum = 0; int T = 0;
        for (int c = 255; c >= 0; c--){
            if (cum + chunk[c] >= RK){
                for (int j = 15; j >= 0; j--){
                    cum += bins[c*16 + j];
                    if (cum >= RK){ T = c*16 + j; break; }
                }
                break;
            }
            cum += chunk[c];
        }
        int Tm = (T > 0) ? T - 1 : 0;   // one bin lower: >=16-code (~0.03) margin vs <=~4-code noise
        s_thr = Tm << 4;
    }
    __syncthreads();
    unsigned int thr = (unsigned int)s_thr;
    int* cand = g_candi + (size_t)b*CAND_MAX;
    for (int i = tid*8; i < RM; i += 2048){
        uint4 pk = *(const uint4*)(row + i);
        unsigned int us[4] = {pk.x, pk.y, pk.z, pk.w};
        #pragma unroll
        for (int q = 0; q < 4; q++){
            unsigned int u = us[q];
            unsigned int k0 = bf16key(u & 0xFFFFu);
            unsigned int k1 = bf16key(u >> 16);
            if (k0 >= thr){ int p = atomicAdd(&s_cnt, 1); if (p < CAND_MAX) cand[p] = i + q*2; }
            if (k1 >= thr){ int p = atomicAdd(&s_cnt, 1); if (p < CAND_MAX) cand[p] = i + q*2 + 1; }
        }
    }
    __syncthreads();
    if (tid == 0) g_ccnt[b] = (s_cnt > CAND_MAX) ? CAND_MAX : s_cnt;
}

// ---------------- compensated-fp32 refinement of candidates + exact top-50 ----------------
__global__ __launch_bounds__(256) void refine_kernel()
{
    int b = blockIdx.x, tid = threadIdx.x;
    __shared__ float q[RD];
    __shared__ float rv[CAND_MAX];
    __shared__ int   ri[CAND_MAX];
    __shared__ int   sn;
    if (tid == 0) sn = g_ccnt[b];
    for (int t = tid; t < RD; t += 256) q[t] = g_qn[b*RD + t];
    __syncthreads();
    int n = sn;
    for (int c = tid; c < n; c += 256){
        int idx = g_candi[(size_t)b*CAND_MAX + c];
        const float* kr = &g_kn[(size_t)idx*RD];
        float sh = 0.f, sl = 0.f;
        #pragma unroll 4
        for (int d = 0; d < RD; d++){
            float a = q[d], w = kr[d];
            float p  = a * w;
            float pe = fmaf(a, w, -p);
            float t  = sh + p;
            float z  = t - sh;
            float e  = (sh - (t - z)) + (p - z);
            sh = t;
            sl += e + pe;
        }
        rv[c] = sh + sl;
        ri[c] = idx;
    }
    __syncthreads();
    for (int c = tid; c < n; c += 256){
        float mv = rv[c]; int mi = ri[c];
        int rank = 0;
        for (int j = 0; j < n; j++){
            float v = rv[j]; int m = ri[j];
            rank += ((v > mv) || (v == mv && m < mi)) ? 1 : 0;
        }
        if (rank < RK){
            g_topv[b*RK + rank] = mv;
            g_topi[b*RK + rank] = mi;
        }
    }
}

// ---------------- softmax attn + context + gather metadata ----------------
__global__ __launch_bounds__(RD) void attn_ctx_kernel(
    const float* __restrict__ fq, const int* __restrict__ tq,
    const float* __restrict__ fb_ctx, float* __restrict__ out_ctx,
    float* __restrict__ out_used)
{
    int b = blockIdx.x, tid = threadIdx.x;
    __shared__ float v[RK];
    __shared__ int   ixs[RK];
    __shared__ float w[RK];
    __shared__ int   uflag;
    if (tid < RK){ v[tid] = g_topv[b*RK + tid]; int id = g_topi[b*RK + tid]; ixs[tid] = (id >= 0) ? id : 0;
                   g_ixs[b*RK + tid] = ixs[tid];
                   g_tgt[b*RK + tid] = (id >= 0) ? max(tq[ixs[tid]], 0) : 0; }
    __syncthreads();
    if (tid == 0){
        float mx = -INFINITY; int u = 0;
        for (int k = 0; k < RK; k++){
            float vk = v[k];
            if (vk > -1e30f){ u = 1; if (vk > mx) mx = vk; }
        }
        float s = 0.f;
        for (int k = 0; k < RK; k++){
            float vk = v[k];
            float wk = (vk > -1e30f) ? expf((vk - mx) * INV_T) : 0.f;
            w[k] = wk; s += wk;
        }
        float inv = 1.0f / fmaxf(s, 1e-12f);
        for (int k = 0; k < RK; k++) w[k] *= inv;
        uflag = u;
        g_used[b] = u;
        out_used[b] = u ? 1.0f : 0.0f;
    }
    __syncthreads();
    if (tid < RK) g_w[b*RK + tid] = w[tid];
    float c = 0.f;
    for (int k = 0; k < RK; k++){
        float wk = w[k];
        if (wk != 0.f) c = fmaf(wk, fq[(size_t)ixs[k]*RD + tid], c);
    }
    out_ctx[b*RD + tid] = uflag ? c : fb_ctx[tid];
}

// ---------------- gemm1 via bf16 mma, 3-term split (K=768) ----------------
__device__ __forceinline__ uint4 lda8_split(
    const float* __restrict__ fq, const float* __restrict__ item_emb,
    int rowf, int rowt, int kg)
{
    int t = kg >> 8, sc = kg & 255;
    const float* src = (sc < 128) ? (fq + (size_t)rowf*RD + sc)
                                  : (item_emb + (size_t)rowt*RD + (sc - 128));
    float4 u = *(const float4*)src;
    float4 v = *(const float4*)(src + 4);
    float xs[8] = {u.x,u.y,u.z,u.w,v.x,v.y,v.z,v.w};
    bool lo = (t == 2);
    uint4 r; unsigned short* p = (unsigned short*)&r;
    #pragma unroll
    for (int i = 0; i < 8; i++){
        __nv_bfloat16 hi = __float2bfloat16(xs[i]);
        p[i] = lo ? __bfloat16_as_ushort(__float2bfloat16(xs[i] - __bfloat162float(hi)))
                  : __bfloat16_as_ushort(hi);
    }
    return r;
}

__global__ __launch_bounds__(256) void gemm1_mma_kernel(
    const float* __restrict__ fq, const float* __restrict__ item_emb,
    const float* __restrict__ b1)
{
    __shared__ __nv_bfloat16 As[128][SPAD];
    __shared__ __nv_bfloat16 Bs[128][SPAD];
    __shared__ int   rid[128];
    __shared__ int   tgd[128];
    __shared__ float wrow[128];

    int tid  = threadIdx.x;
    int lane = tid & 31;
    int wid  = tid >> 5;
    int wm   = wid >> 2;
    int wn   = wid & 3;
    int c0  = blockIdx.x * 128;
    int nr0 = blockIdx.y * 128;

    if (tid < 128){
        rid[tid]  = g_ixs[nr0 + tid];
        tgd[tid]  = g_tgt[nr0 + tid];
        wrow[tid] = g_w[nr0 + tid];
    }
    __syncthreads();

    float acc[4][4][4];
    #pragma unroll
    for (int i = 0; i < 4; i++)
        #pragma unroll
        for (int j = 0; j < 4; j++)
            #pragma unroll
            for (int r = 0; r < 4; r++) acc[i][j][r] = 0.f;

    int s0 = tid, s1 = tid + 256;
    int ra0 = s0 >> 2, ca0 = (s0 & 3) * 8;
    int ra1 = s1 >> 2, ca1 = (s1 & 3) * 8;
    const __nv_bfloat16* wbase = g_w1t + (size_t)c0*KE1;

    uint4 pa0 = lda8_split(fq, item_emb, rid[ra0], tgd[ra0], ca0);
    uint4 pa1 = lda8_split(fq, item_emb, rid[ra1], tgd[ra1], ca1);
    uint4 pb0 = *(const uint4*)(wbase + (size_t)ra0*KE1 + ca0);
    uint4 pb1 = *(const uint4*)(wbase + (size_t)ra1*KE1 + ca1);

    for (int kc = 0; kc < KE1; kc += 32){
        __syncthreads();
        *(uint4*)&As[ra0][ca0] = pa0;
        *(uint4*)&As[ra1][ca1] = pa1;
        *(uint4*)&Bs[ra0][ca0] = pb0;
        *(uint4*)&Bs[ra1][ca1] = pb1;
        __syncthreads();
        int kn = kc + 32;
        if (kn < KE1){
            pa0 = lda8_split(fq, item_emb, rid[ra0], tgd[ra0], kn + ca0);
            pa1 = lda8_split(fq, item_emb, rid[ra1], tgd[ra1], kn + ca1);
            pb0 = *(const uint4*)(wbase + (size_t)ra0*KE1 + kn + ca0);
            pb1 = *(const uint4*)(wbase + (size_t)ra1*KE1 + kn + ca1);
        }
        #pragma unroll
        for (int ks = 0; ks < 2; ks++){
            int kk = ks * 16;
            uint32_t af[4][4], bf[4][2];
            #pragma unroll
            for (int mi = 0; mi < 4; mi++){
                uint32_t addr = (uint32_t)__cvta_generic_to_shared(
                    &As[wm*64 + mi*16 + (lane & 15)][kk + (lane >> 4)*8]);
                asm volatile("ldmatrix.sync.aligned.m8n8.x4.shared.b16 {%0,%1,%2,%3}, [%4];"
                    : "=r"(af[mi][0]), "=r"(af[mi][1]), "=r"(af[mi][2]), "=r"(af[mi][3])
                    : "r"(addr));
            }
            #pragma unroll
            for (int ni = 0; ni < 4; ni++){
                uint32_t addr = (uint32_t)__cvta_generic_to_shared(
                    &Bs[wn*32 + ni*8 + (lane & 7)][kk + ((lane >> 3) & 1)*8]);
                asm volatile("ldmatrix.sync.aligned.m8n8.x2.shared.b16 {%0,%1}, [%2];"
                    : "=r"(bf[ni][0]), "=r"(bf[ni][1]) : "r"(addr));
            }
            #pragma unroll
            for (int mi = 0; mi < 4; mi++)
                #pragma unroll
                for (int ni = 0; ni < 4; ni++){
                    asm volatile(
                        "mma.sync.aligned.m16n8k16.row.col.f32.bf16.bf16.f32 "
                        "{%0,%1,%2,%3}, {%4,%5,%6,%7}, {%8,%9}, {%0,%1,%2,%3};"
                        : "+f"(acc[mi][ni][0]), "+f"(acc[mi][ni][1]),
                          "+f"(acc[mi][ni][2]), "+f"(acc[mi][ni][3])
                        : "r"(af[mi][0]), "r"(af[mi][1]), "r"(af[mi][2]), "r"(af[mi][3]),
                          "r"(bf[ni][0]), "r"(bf[ni][1]));
                }
        }
    }

    #pragma unroll
    for (int mi = 0; mi < 4; mi++){
        int rl0 = wm*64 + mi*16 + (lane >> 2);
        #pragma unroll
        for (int ni = 0; ni < 4; ni++){
            int cl = wn*32 + ni*8 + (lane & 3)*2;
            int c = c0 + cl;
            float bb0 = b1[c], bb1 = b1[c+1];
            #pragma unroll
            for (int h = 0; h < 2; h++){
                int rr = rl0 + h*8;
                float x0 = acc[mi][ni][h*2+0] + bb0;
                float x1 = acc[mi][ni][h*2+1] + bb1;
                float g0 = 0.5f * x0 * (1.0f + erff(x0 * 0.70710678118654752f));
                float g1 = 0.5f * x1 * (1.0f + erff(x1 * 0.70710678118654752f));
                float wk = wrow[rr];
                float2 v; v.x = wk * g0; v.y = wk * g1;
                *(float2*)&g_H[(size_t)(nr0 + rr)*RC + c] = v;
            }
        }
    }
}

__global__ __launch_bounds__(RC) void reduce_kernel()
{
    int b = blockIdx.x, c = threadIdx.x;
    float s = 0.f;
    const float* base = g_H + (size_t)b*RK*RC + c;
    #pragma unroll 10
    for (int k = 0; k < RK; k++) s += base[k*RC];
    g_S[b*RC + c] = s;
}

__global__ __launch_bounds__(RC) void gemm2_kernel(
    const float* __restrict__ W2, const float* __restrict__ b2,
    const float* __restrict__ fb_sum, float* __restrict__ out_sum)
{
    int b = blockIdx.x, c = threadIdx.x;
    __shared__ float sr[RC];
    sr[c] = g_S[b*RC + c];
    __syncthreads();
    float a = b2[c];
    #pragma unroll 8
    for (int d = 0; d < RC; d++)
        a = fmaf(sr[d], W2[d*RC + c], a);
    out_sum[b*RC + c] = g_used[b] ? a : fb_sum[c];
}

// ---------------- launch ----------------
extern "C" void kernel_launch(void* const* d_in, const int* in_sizes, int n_in,
                              void* d_out, int out_size)
{
    const float* current_repr = (const float*)d_in[0];
    const int*   session_ids  = (const int*)  d_in[1];
    const float* item_emb     = (const float*)d_in[2];
    const float* feature_q    = (const float*)d_in[3];
    const int*   session_q    = (const int*)  d_in[4];
    const int*   target_q     = (const int*)  d_in[5];
    const float* Wq = (const float*)d_in[6];
    const float* bq = (const float*)d_in[7];
    const float* Wk = (const float*)d_in[8];
    const float* bk = (const float*)d_in[9];
    const float* W1 = (const float*)d_in[10];
    const float* b1 = (const float*)d_in[11];
    const float* W2 = (const float*)d_in[12];
    const float* b2 = (const float*)d_in[13];
    const float* fb_ctx = (const float*)d_in[14];
    const float* fb_sum = (const float*)d_in[15];

    float* out = (float*)d_out;
    float* out_ctx  = out;
    float* out_sum  = out + (size_t)RB*RD;
    float* out_used = out + (size_t)RB*RD + (size_t)RB*RC;

    float *d_qn, *d_kn;
    __nv_bfloat16 *d_qh, *d_kh;
    cudaGetSymbolAddress((void**)&d_qn, g_qn);
    cudaGetSymbolAddress((void**)&d_kn, g_kn);
    cudaGetSymbolAddress((void**)&d_qh, g_qh);
    cudaGetSymbolAddress((void**)&d_kh, g_kh);

    // launch index 3 = ncu capture slot -> topsel
    proj_kernel<<<RB/KP_ROWS, 128>>>(current_repr, Wq, bq, d_qn, d_qh);
    proj_kernel<<<RM/KP_ROWS, 128>>>(feature_q, Wk, bk, d_kn, d_kh);
    dim3 sg(RMP/128, RB/128);
    sims_mma_kernel<<<sg, 256>>>(session_ids, session_q);
    topsel_kernel<<<RB, 256>>>();
    w1split_kernel<<<(RC*RC+255)/256, 256>>>(W1);
    refine_kernel<<<RB, 256>>>();
    attn_ctx_kernel<<<RB, RD>>>(feature_q, target_q, fb_ctx, out_ctx, out_used);
    dim3 g1(RC/128, RNR/128);
    gemm1_mma_kernel<<<g1, 256>>>(feature_q, item_emb, b1);
    reduce_kernel<<<RB, RC>>>();
    gemm2_kernel<<<RB, RC>>>(W2, b2, fb_sum, out_sum);
}

// round 17
// speedup vs baseline: 4.3902x; 1.0371x over previous
#include <cuda_runtime.h>
#include <cuda_bf16.h>
#include <cstdint>
#include <math.h>

#define RB   1024
#define RD   128
#define RC   256
#define RM   100000
#define RMP  100096          // M padded to 128
#define RK   50
#define RNR  (RB*RK)         // 51200
#define HBINS 4096
#define CAND_MAX 2048
#define INV_T 14.285714285714286f

// ---------------- device scratch ----------------
__device__ __align__(256) float g_qn[RB*RD];
__device__ __align__(256) float g_kn[(size_t)RMP*RD];   // zero-init
__device__ __align__(256) __nv_bfloat16 g_qh[RB*RD];
__device__ __align__(256) __nv_bfloat16 g_kh[(size_t)RMP*RD];  // padded rows stay 0
__device__ __align__(256) __nv_bfloat16 g_w1s[(size_t)RC*512]; // [c][0..255]=hi, [c][256..511]=lo
__device__ __align__(256) __nv_bfloat16 g_simsb[(size_t)RB*RMP];
__device__ __align__(256) int   g_candi[(size_t)RB*CAND_MAX];
__device__ __align__(256) int   g_ccnt[RB];
__device__ __align__(256) float g_topv[RB*RK];
__device__ __align__(256) int   g_topi[RB*RK];
__device__ __align__(256) float g_w[RNR];
__device__ __align__(256) int   g_tgt[RNR];
__device__ __align__(256) int   g_ixs[RNR];
__device__ __align__(256) int   g_used[RB];
__device__ __align__(256) float g_H[(size_t)RNR*RC];
__device__ __align__(256) float g_S[RB*RC];

#define SPAD 40     // bf16 per smem row (32 data + 8 pad)

// ---------------- SIMT projection + l2norm, exact fp32 (order-preserving, 64 rows) ----------------
#define KP_ROWS 64
__global__ __launch_bounds__(128) void proj_kernel(
    const float* __restrict__ X, const float* __restrict__ W,
    const float* __restrict__ bias, float* __restrict__ out,
    __nv_bfloat16* __restrict__ out_bf, int nrows)
{
    __shared__ float xs[KP_ROWS][RD];
    __shared__ float os[KP_ROWS][RD+1];
    __shared__ float n4[KP_ROWS][4];
    int tid = threadIdx.x;
    int base = blockIdx.x * KP_ROWS;
    #pragma unroll
    for (int rr = 0; rr < KP_ROWS; rr++){
        int r = min(base + rr, nrows - 1);
        xs[rr][tid] = X[(size_t)r*RD + tid];
    }
    __syncthreads();
    float acc[KP_ROWS];
    float bv = bias[tid];
    #pragma unroll
    for (int rr = 0; rr < KP_ROWS; rr++) acc[rr] = bv;
    // identical fmaf chain order per row (ascending d)
    for (int d = 0; d < RD; d += 4){
        float w0 = W[(d+0)*RD + tid];
        float w1 = W[(d+1)*RD + tid];
        float w2 = W[(d+2)*RD + tid];
        float w3 = W[(d+3)*RD + tid];
        #pragma unroll
        for (int rr = 0; rr < KP_ROWS; rr++){
            float4 xv = *(const float4*)&xs[rr][d];
            float a = acc[rr];
            a = fmaf(xv.x, w0, a);
            a = fmaf(xv.y, w1, a);
            a = fmaf(xv.z, w2, a);
            a = fmaf(xv.w, w3, a);
            acc[rr] = a;
        }
    }
    #pragma unroll
    for (int rr = 0; rr < KP_ROWS; rr++) os[rr][tid] = acc[rr];
    __syncthreads();
    {
        int q = tid & 1;
        #pragma unroll
        for (int g = 0; g < KP_ROWS/2; g++){
            int rr = (tid >> 1) + g*64;
            if (rr < KP_ROWS){
                // two threads per row, 64 elems each; combine as (q0+q1)+(q2+q3) == same as before? 
                // keep exact prior order: 4 quarters summed in fixed order by one thread
            }
        }
    }
    // per-row norm: quarters in fixed order (matches prior bit pattern)
    if (tid < KP_ROWS){
        int rr = tid;
        float s0 = 0.f, s1 = 0.f, s2 = 0.f, s3 = 0.f;
        #pragma unroll
        for (int j = 0; j < 32; j++){ float v = os[rr][j];      s0 = fmaf(v, v, s0); }
        #pragma unroll
        for (int j = 0; j < 32; j++){ float v = os[rr][32 + j]; s1 = fmaf(v, v, s1); }
        #pragma unroll
        for (int j = 0; j < 32; j++){ float v = os[rr][64 + j]; s2 = fmaf(v, v, s2); }
        #pragma unroll
        for (int j = 0; j < 32; j++){ float v = os[rr][96 + j]; s3 = fmaf(v, v, s3); }
        float t = s0 + s1 + s2 + s3;
        n4[rr][0] = 1.0f / fmaxf(sqrtf(t), 1e-12f);
    }
    __syncthreads();
    #pragma unroll
    for (int rr = 0; rr < KP_ROWS; rr++){
        int r = base + rr;
        if (r < nrows){
            float v = os[rr][tid] * n4[rr][0];
            out[(size_t)r*RD + tid] = v;
            out_bf[(size_t)r*RD + tid] = __float2bfloat16(v);
        }
    }
}

// ---------------- W1 hi/lo split, transposed to [c][512] ----------------
__global__ __launch_bounds__(256) void w1split_kernel(const float* __restrict__ W1){
    int idx = blockIdx.x*256 + threadIdx.x;   // k*256 + c
    if (idx >= RC*RC) return;
    int k = idx >> 8, c = idx & 255;
    float x = W1[idx];
    __nv_bfloat16 hi = __float2bfloat16(x);
    __nv_bfloat16 lo = __float2bfloat16(x - __bfloat162float(hi));
    size_t b = (size_t)c*512 + k;
    g_w1s[b] = hi; g_w1s[b+256] = lo;
}

// ---------------- sims = qh @ kh^T via bf16 mma, K=128; bf16 output, staged stores ----------------
__global__ __launch_bounds__(256) void sims_mma_kernel(
    const int* __restrict__ sessid, const int* __restrict__ sq)
{
    __shared__ __nv_bfloat16 sAB[2*128*SPAD];
    __nv_bfloat16 (*As)[SPAD] = (__nv_bfloat16(*)[SPAD])sAB;
    __nv_bfloat16 (*Bs)[SPAD] = (__nv_bfloat16(*)[SPAD])(sAB + 128*SPAD);
    __shared__ int sids[128];
    __shared__ int msess[128];

    int tid  = threadIdx.x;
    int lane = tid & 31;
    int wid  = tid >> 5;
    int wm   = wid >> 2;
    int wn   = wid & 3;
    int m0 = blockIdx.x * 128;
    int b0 = blockIdx.y * 128;

    if (tid < 128){
        sids[tid]  = sessid[b0 + tid];
        msess[tid] = (m0 + tid < RM) ? sq[m0 + tid] : -1;
    }

    float acc[4][4][4];
    #pragma unroll
    for (int i = 0; i < 4; i++)
        #pragma unroll
        for (int j = 0; j < 4; j++)
            #pragma unroll
            for (int r = 0; r < 4; r++) acc[i][j][r] = 0.f;

    const __nv_bfloat16* qbase = g_qh + (size_t)b0*RD;
    const __nv_bfloat16* kbase = g_kh + (size_t)m0*RD;
    int s0 = tid, s1 = tid + 256;
    int ra0 = s0 >> 2, ca0 = (s0 & 3) * 8;
    int ra1 = s1 >> 2, ca1 = (s1 & 3) * 8;

    uint4 pa0 = *(const uint4*)(qbase + (size_t)ra0*RD + ca0);
    uint4 pa1 = *(const uint4*)(qbase + (size_t)ra1*RD + ca1);
    uint4 pb0 = *(const uint4*)(kbase + (size_t)ra0*RD + ca0);
    uint4 pb1 = *(const uint4*)(kbase + (size_t)ra1*RD + ca1);

    for (int kc = 0; kc < RD; kc += 32){
        __syncthreads();
        *(uint4*)&As[ra0][ca0] = pa0;
        *(uint4*)&As[ra1][ca1] = pa1;
        *(uint4*)&Bs[ra0][ca0] = pb0;
        *(uint4*)&Bs[ra1][ca1] = pb1;
        __syncthreads();
        int kn = kc + 32;
        if (kn < RD){
            pa0 = *(const uint4*)(qbase + (size_t)ra0*RD + kn + ca0);
            pa1 = *(const uint4*)(qbase + (size_t)ra1*RD + kn + ca1);
            pb0 = *(const uint4*)(kbase + (size_t)ra0*RD + kn + ca0);
            pb1 = *(const uint4*)(kbase + (size_t)ra1*RD + kn + ca1);
        }
        #pragma unroll
        for (int ks = 0; ks < 2; ks++){
            int kk = ks * 16;
            uint32_t af[4][4], bf[4][2];
            #pragma unroll
            for (int mi = 0; mi < 4; mi++){
                uint32_t addr = (uint32_t)__cvta_generic_to_shared(
                    &As[wm*64 + mi*16 + (lane & 15)][kk + (lane >> 4)*8]);
                asm volatile("ldmatrix.sync.aligned.m8n8.x4.shared.b16 {%0,%1,%2,%3}, [%4];"
                    : "=r"(af[mi][0]), "=r"(af[mi][1]), "=r"(af[mi][2]), "=r"(af[mi][3])
                    : "r"(addr));
            }
            #pragma unroll
            for (int ni = 0; ni < 4; ni++){
                uint32_t addr = (uint32_t)__cvta_generic_to_shared(
                    &Bs[wn*32 + ni*8 + (lane & 7)][kk + ((lane >> 3) & 1)*8]);
                asm volatile("ldmatrix.sync.aligned.m8n8.x2.shared.b16 {%0,%1}, [%2];"
                    : "=r"(bf[ni][0]), "=r"(bf[ni][1]) : "r"(addr));
            }
            #pragma unroll
            for (int mi = 0; mi < 4; mi++)
                #pragma unroll
                for (int ni = 0; ni < 4; ni++){
                    asm volatile(
                        "mma.sync.aligned.m16n8k16.row.col.f32.bf16.bf16.f32 "
                        "{%0,%1,%2,%3}, {%4,%5,%6,%7}, {%8,%9}, {%0,%1,%2,%3};"
                        : "+f"(acc[mi][ni][0]), "+f"(acc[mi][ni][1]),
                          "+f"(acc[mi][ni][2]), "+f"(acc[mi][ni][3])
                        : "r"(af[mi][0]), "r"(af[mi][1]), "r"(af[mi][2]), "r"(af[mi][3]),
                          "r"(bf[ni][0]), "r"(bf[ni][1]));
                }
        }
    }

    // epilogue: mask + stage 64-row halves in smem, then coalesced 16B stores
    const unsigned short NEGINF = 0xFF80;
    __nv_bfloat16* stg = sAB;     // [64][136]
    #pragma unroll
    for (int p = 0; p < 2; p++){
        __syncthreads();
        if (wm == p){
            #pragma unroll
            for (int mi = 0; mi < 4; mi++){
                #pragma unroll
                for (int h = 0; h < 2; h++){
                    int lr = mi*16 + (lane >> 2) + h*8;      // 0..63
                    int sid = sids[p*64 + lr];
                    #pragma unroll
                    for (int ni = 0; ni < 4; ni++){
                        int cl = wn*32 + ni*8 + (lane & 3)*2;
                        __nv_bfloat162 hv = __float22bfloat162_rn(
                            make_float2(acc[mi][ni][h*2+0], acc[mi][ni][h*2+1]));
                        unsigned int u = *(unsigned int*)&hv;
                        if (msess[cl]   == sid) u = (u & 0xFFFF0000u) | NEGINF;
                        if (msess[cl+1] == sid) u = (u & 0x0000FFFFu) | ((unsigned)NEGINF << 16);
                        *(unsigned int*)&stg[lr*136 + cl] = u;
                    }
                }
            }
        }
        __syncthreads();
        int lrow = tid >> 2, t4 = tid & 3;
        #pragma unroll
        for (int i = 0; i < 4; i++){
            int seg = t4*4 + i;
            uint4 v = *(uint4*)&stg[lrow*136 + seg*8];
            *(uint4*)&g_simsb[(size_t)(b0 + p*64 + lrow)*RMP + m0 + seg*8] = v;
        }
    }
}

// ---------------- histogram-threshold candidate selection (no flushes) ----------------
__device__ __forceinline__ unsigned int bf16key(unsigned int h){
    return (h & 0x8000u) ? (0xFFFFu - h) : (h | 0x8000u);
}

__global__ __launch_bounds__(256) void topsel_kernel()
{
    int b = blockIdx.x, tid = threadIdx.x;
    __shared__ unsigned int bins[HBINS];
    __shared__ unsigned int chunk[256];
    __shared__ int s_thr;
    __shared__ int s_cnt;
    for (int i = tid; i < HBINS; i += 256) bins[i] = 0;
    if (tid == 0) s_cnt = 0;
    __syncthreads();
    const __nv_bfloat16* row = g_simsb + (size_t)b*RMP;
    for (int i = tid*8; i < RM; i += 2048){
        uint4 pk = *(const uint4*)(row + i);
        unsigned int us[4] = {pk.x, pk.y, pk.z, pk.w};
        #pragma unroll
        for (int q = 0; q < 4; q++){
            unsigned int u = us[q];
            atomicAdd(&bins[bf16key(u & 0xFFFFu) >> 4], 1u);
            atomicAdd(&bins[bf16key(u >> 16) >> 4], 1u);
        }
    }
    __syncthreads();
    unsigned int cs = 0;
    #pragma unroll
    for (int j = 0; j < 16; j++) cs += bins[tid*16 + j];
    chunk[tid] = cs;
    __syncthreads();
    if (tid == 0){
        unsigned int cum = 0; int T = 0;
        for (int c = 255; c >= 0; c--){
            if (cum + chunk[c] >= RK){
                for (int j = 15; j >= 0; j--){
                    cum += bins[c*16 + j];
                    if (cum >= RK){ T = c*16 + j; break; }
                }
                break;
            }
            cum += chunk[c];
        }
        int Tm = (T > 0) ? T - 1 : 0;
        s_thr = Tm << 4;
    }
    __syncthreads();
    unsigned int thr = (unsigned int)s_thr;
    int* cand = g_candi + (size_t)b*CAND_MAX;
    for (int i = tid*8; i < RM; i += 2048){
        uint4 pk = *(const uint4*)(row + i);
        unsigned int us[4] = {pk.x, pk.y, pk.z, pk.w};
        #pragma unroll
        for (int q = 0; q < 4; q++){
            unsigned int u = us[q];
            unsigned int k0 = bf16key(u & 0xFFFFu);
            unsigned int k1 = bf16key(u >> 16);
            if (k0 >= thr){ int p = atomicAdd(&s_cnt, 1); if (p < CAND_MAX) cand[p] = i + q*2; }
            if (k1 >= thr){ int p = atomicAdd(&s_cnt, 1); if (p < CAND_MAX) cand[p] = i + q*2 + 1; }
        }
    }
    __syncthreads();
    if (tid == 0) g_ccnt[b] = (s_cnt > CAND_MAX) ? CAND_MAX : s_cnt;
}

// ---------------- compensated-fp32 refinement of candidates + exact top-50 ----------------
__global__ __launch_bounds__(256) void refine_kernel()
{
    int b = blockIdx.x, tid = threadIdx.x;
    __shared__ float q[RD];
    __shared__ float rv[CAND_MAX];
    __shared__ int   ri[CAND_MAX];
    __shared__ int   sn;
    if (tid == 0) sn = g_ccnt[b];
    for (int t = tid; t < RD; t += 256) q[t] = g_qn[b*RD + t];
    __syncthreads();
    int n = sn;
    for (int c = tid; c < n; c += 256){
        int idx = g_candi[(size_t)b*CAND_MAX + c];
        const float* kr = &g_kn[(size_t)idx*RD];
        float sh = 0.f, sl = 0.f;
        #pragma unroll 4
        for (int d = 0; d < RD; d++){
            float a = q[d], w = kr[d];
            float p  = a * w;
            float pe = fmaf(a, w, -p);
            float t  = sh + p;
            float z  = t - sh;
            float e  = (sh - (t - z)) + (p - z);
            sh = t;
            sl += e + pe;
        }
        rv[c] = sh + sl;
        ri[c] = idx;
    }
    __syncthreads();
    for (int c = tid; c < n; c += 256){
        float mv = rv[c]; int mi = ri[c];
        int rank = 0;
        for (int j = 0; j < n; j++){
            float v = rv[j]; int m = ri[j];
            rank += ((v > mv) || (v == mv && m < mi)) ? 1 : 0;
        }
        if (rank < RK){
            g_topv[b*RK + rank] = mv;
            g_topi[b*RK + rank] = mi;
        }
    }
}

// ---------------- softmax attn + context + gather metadata ----------------
__global__ __launch_bounds__(RD) void attn_ctx_kernel(
    const float* __restrict__ fq, const int* __restrict__ tq,
    const float* __restrict__ fb_ctx, float* __restrict__ out_ctx,
    float* __restrict__ out_used)
{
    int b = blockIdx.x, tid = threadIdx.x;
    __shared__ float v[RK];
    __shared__ int   ixs[RK];
    __shared__ float w[RK];
    __shared__ int   uflag;
    if (tid < RK){ v[tid] = g_topv[b*RK + tid]; int id = g_topi[b*RK + tid]; ixs[tid] = (id >= 0) ? id : 0;
                   g_ixs[b*RK + tid] = ixs[tid];
                   g_tgt[b*RK + tid] = (id >= 0) ? max(tq[ixs[tid]], 0) : 0; }
    __syncthreads();
    if (tid == 0){
        float mx = -INFINITY; int u = 0;
        for (int k = 0; k < RK; k++){
            float vk = v[k];
            if (vk > -1e30f){ u = 1; if (vk > mx) mx = vk; }
        }
        float s = 0.f;
        for (int k = 0; k < RK; k++){
            float vk = v[k];
            float wk = (vk > -1e30f) ? expf((vk - mx) * INV_T) : 0.f;
            w[k] = wk; s += wk;
        }
        float inv = 1.0f / fmaxf(s, 1e-12f);
        for (int k = 0; k < RK; k++) w[k] *= inv;
        uflag = u;
        g_used[b] = u;
        out_used[b] = u ? 1.0f : 0.0f;
    }
    __syncthreads();
    if (tid < RK) g_w[b*RK + tid] = w[tid];
    float c = 0.f;
    for (int k = 0; k < RK; k++){
        float wk = w[k];
        if (wk != 0.f) c = fmaf(wk, fq[(size_t)ixs[k]*RD + tid], c);
    }
    out_ctx[b*RD + tid] = uflag ? c : fb_ctx[tid];
}

// ---------------- gemm1 via bf16 mma, single K pass, 3 term-products ----------------
__device__ __forceinline__ void lda8_hl(
    const float* __restrict__ fq, const float* __restrict__ item_emb,
    int rowf, int rowt, int kg, uint4& rh, uint4& rl)
{
    const float* src = (kg < 128) ? (fq + (size_t)rowf*RD + kg)
                                  : (item_emb + (size_t)rowt*RD + (kg - 128));
    float4 u = *(const float4*)src;
    float4 v = *(const float4*)(src + 4);
    float xs[8] = {u.x,u.y,u.z,u.w,v.x,v.y,v.z,v.w};
    unsigned short* ph = (unsigned short*)&rh;
    unsigned short* pl = (unsigned short*)&rl;
    #pragma unroll
    for (int i = 0; i < 8; i++){
        __nv_bfloat16 hi = __float2bfloat16(xs[i]);
        ph[i] = __bfloat16_as_ushort(hi);
        pl[i] = __bfloat16_as_ushort(__float2bfloat16(xs[i] - __bfloat162float(hi)));
    }
}

__global__ __launch_bounds__(256) void gemm1_mma_kernel(
    const float* __restrict__ fq, const float* __restrict__ item_emb,
    const float* __restrict__ b1)
{
    __shared__ __nv_bfloat16 Ah[128][SPAD];
    __shared__ __nv_bfloat16 Al[128][SPAD];
    __shared__ __nv_bfloat16 Bh[128][SPAD];
    __shared__ __nv_bfloat16 Bl[128][SPAD];
    __shared__ int   rid[128];
    __shared__ int   tgd[128];
    __shared__ float wrow[128];

    int tid  = threadIdx.x;
    int lane = tid & 31;
    int wid  = tid >> 5;
    int wm   = wid >> 2;
    int wn   = wid & 3;
    int c0  = blockIdx.x * 128;
    int nr0 = blockIdx.y * 128;

    if (tid < 128){
        rid[tid]  = g_ixs[nr0 + tid];
        tgd[tid]  = g_tgt[nr0 + tid];
        wrow[tid] = g_w[nr0 + tid];
    }
    __syncthreads();

    float acc[4][4][4];
    #pragma unroll
    for (int i = 0; i < 4; i++)
        #pragma unroll
        for (int j = 0; j < 4; j++)
            #pragma unroll
            for (int r = 0; r < 4; r++) acc[i][j][r] = 0.f;

    int s0 = tid, s1 = tid + 256;
    int ra0 = s0 >> 2, ca0 = (s0 & 3) * 8;
    int ra1 = s1 >> 2, ca1 = (s1 & 3) * 8;
    const __nv_bfloat16* wbase = g_w1s + (size_t)c0*512;

    for (int kc = 0; kc < 256; kc += 32){
        __syncthreads();
        {
            uint4 h0, l0, h1, l1;
            lda8_hl(fq, item_emb, rid[ra0], tgd[ra0], kc + ca0, h0, l0);
            lda8_hl(fq, item_emb, rid[ra1], tgd[ra1], kc + ca1, h1, l1);
            *(uint4*)&Ah[ra0][ca0] = h0;  *(uint4*)&Al[ra0][ca0] = l0;
            *(uint4*)&Ah[ra1][ca1] = h1;  *(uint4*)&Al[ra1][ca1] = l1;
            *(uint4*)&Bh[ra0][ca0] = *(const uint4*)(wbase + (size_t)ra0*512 + kc + ca0);
            *(uint4*)&Bh[ra1][ca1] = *(const uint4*)(wbase + (size_t)ra1*512 + kc + ca1);
            *(uint4*)&Bl[ra0][ca0] = *(const uint4*)(wbase + (size_t)ra0*512 + 256 + kc + ca0);
            *(uint4*)&Bl[ra1][ca1] = *(const uint4*)(wbase + (size_t)ra1*512 + 256 + kc + ca1);
        }
        __syncthreads();
        #pragma unroll
        for (int ks = 0; ks < 2; ks++){
            int kk = ks * 16;
            uint32_t ah[4][4], bh[4][2], bl[4][2];
            #pragma unroll
            for (int mi = 0; mi < 4; mi++){
                uint32_t addr = (uint32_t)__cvta_generic_to_shared(
                    &Ah[wm*64 + mi*16 + (lane & 15)][kk + (lane >> 4)*8]);
                asm volatile("ldmatrix.sync.aligned.m8n8.x4.shared.b16 {%0,%1,%2,%3}, [%4];"
                    : "=r"(ah[mi][0]), "=r"(ah[mi][1]), "=r"(ah[mi][2]), "=r"(ah[mi][3])
                    : "r"(addr));
            }
            #pragma unroll
            for (int ni = 0; ni < 4; ni++){
                uint32_t addr = (uint32_t)__cvta_generic_to_shared(
                    &Bh[wn*32 + ni*8 + (lane & 7)][kk + ((lane >> 3) & 1)*8]);
                asm volatile("ldmatrix.sync.aligned.m8n8.x2.shared.b16 {%0,%1}, [%2];"
                    : "=r"(bh[ni][0]), "=r"(bh[ni][1]) : "r"(addr));
            }
            #pragma unroll
            for (int ni = 0; ni < 4; ni++){
                uint32_t addr = (uint32_t)__cvta_generic_to_shared(
                    &Bl[wn*32 + ni*8 + (lane & 7)][kk + ((lane >> 3) & 1)*8]);
                asm volatile("ldmatrix.sync.aligned.m8n8.x2.shared.b16 {%0,%1}, [%2];"
                    : "=r"(bl[ni][0]), "=r"(bl[ni][1]) : "r"(addr));
            }
            #pragma unroll
            for (int mi = 0; mi < 4; mi++)
                #pragma unroll
                for (int ni = 0; ni < 4; ni++){
                    asm volatile(
                        "mma.sync.aligned.m16n8k16.row.col.f32.bf16.bf16.f32 "
                        "{%0,%1,%2,%3}, {%4,%5,%6,%7}, {%8,%9}, {%0,%1,%2,%3};"
                        : "+f"(acc[mi][ni][0]), "+f"(acc[mi][ni][1]),
                          "+f"(acc[mi][ni][2]), "+f"(acc[mi][ni][3])
                        : "r"(ah[mi][0]), "r"(ah[mi][1]), "r"(ah[mi][2]), "r"(ah[mi][3]),
                          "r"(bh[ni][0]), "r"(bh[ni][1]));
                    asm volatile(
                        "mma.sync.aligned.m16n8k16.row.col.f32.bf16.bf16.f32 "
                        "{%0,%1,%2,%3}, {%4,%5,%6,%7}, {%8,%9}, {%0,%1,%2,%3};"
                        : "+f"(acc[mi][ni][0]), "+f"(acc[mi][ni][1]),
                          "+f"(acc[mi][ni][2]), "+f"(acc[mi][ni][3])
                        : "r"(ah[mi][0]), "r"(ah[mi][1]), "r"(ah[mi][2]), "r"(ah[mi][3]),
                          "r"(bl[ni][0]), "r"(bl[ni][1]));
                }
            uint32_t al[4][4];
            #pragma unroll
            for (int mi = 0; mi < 4; mi++){
                uint32_t addr = (uint32_t)__cvta_generic_to_shared(
                    &Al[wm*64 + mi*16 + (lane & 15)][kk + (lane >> 4)*8]);
                asm volatile("ldmatrix.sync.aligned.m8n8.x4.shared.b16 {%0,%1,%2,%3}, [%4];"
                    : "=r"(al[mi][0]), "=r"(al[mi][1]), "=r"(al[mi][2]), "=r"(al[mi][3])
                    : "r"(addr));
            }
            #pragma unroll
            for (int mi = 0; mi < 4; mi++)
                #pragma unroll
                for (int ni = 0; ni < 4; ni++){
                    asm volatile(
                        "mma.sync.aligned.m16n8k16.row.col.f32.bf16.bf16.f32 "
                        "{%0,%1,%2,%3}, {%4,%5,%6,%7}, {%8,%9}, {%0,%1,%2,%3};"
                        : "+f"(acc[mi][ni][0]), "+f"(acc[mi][ni][1]),
                          "+f"(acc[mi][ni][2]), "+f"(acc[mi][ni][3])
                        : "r"(al[mi][0]), "r"(al[mi][1]), "r"(al[mi][2]), "r"(al[mi][3]),
                          "r"(bh[ni][0]), "r"(bh[ni][1]));
                }
        }
    }

    #pragma unroll
    for (int mi = 0; mi < 4; mi++){
        int rl0 = wm*64 + mi*16 + (lane >> 2);
        #pragma unroll
        for (int ni = 0; ni < 4; ni++){
            int cl = wn*32 + ni*8 + (lane & 3)*2;
            int c = c0 + cl;
            float bb0 = b1[c], bb1 = b1[c+1];
            #pragma unroll
            for (int h = 0; h < 2; h++){
                int rr = rl0 + h*8;
                float x0 = acc[mi][ni][h*2+0] + bb0;
                float x1 = acc[mi][ni][h*2+1] + bb1;
                float g0 = 0.5f * x0 * (1.0f + erff(x0 * 0.70710678118654752f));
                float g1 = 0.5f * x1 * (1.0f + erff(x1 * 0.70710678118654752f));
                float wk = wrow[rr];
                float2 v; v.x = wk * g0; v.y = wk * g1;
                *(float2*)&g_H[(size_t)(nr0 + rr)*RC + c] = v;
            }
        }
    }
}

__global__ __launch_bounds__(RC) void reduce_kernel()
{
    int b = blockIdx.x, c = threadIdx.x;
    float s = 0.f;
    const float* base = g_H + (size_t)b*RK*RC + c;
    #pragma unroll 10
    for (int k = 0; k < RK; k++) s += base[k*RC];
    g_S[b*RC + c] = s;
}

__global__ __launch_bounds__(RC) void gemm2_kernel(
    const float* __restrict__ W2, const float* __restrict__ b2,
    const float* __restrict__ fb_sum, float* __restrict__ out_sum)
{
    int b = blockIdx.x, c = threadIdx.x;
    __shared__ float sr[RC];
    sr[c] = g_S[b*RC + c];
    __syncthreads();
    float a = b2[c];
    #pragma unroll 8
    for (int d = 0; d < RC; d++)
        a = fmaf(sr[d], W2[d*RC + c], a);
    out_sum[b*RC + c] = g_used[b] ? a : fb_sum[c];
}

// ---------------- launch ----------------
extern "C" void kernel_launch(void* const* d_in, const int* in_sizes, int n_in,
                              void* d_out, int out_size)
{
    const float* current_repr = (const float*)d_in[0];
    const int*   session_ids  = (const int*)  d_in[1];
    const float* item_emb     = (const float*)d_in[2];
    const float* feature_q    = (const float*)d_in[3];
    const int*   session_q    = (const int*)  d_in[4];
    const int*   target_q     = (const int*)  d_in[5];
    const float* Wq = (const float*)d_in[6];
    const float* bq = (const float*)d_in[7];
    const float* Wk = (const float*)d_in[8];
    const float* bk = (const float*)d_in[9];
    const float* W1 = (const float*)d_in[10];
    const float* b1 = (const float*)d_in[11];
    const float* W2 = (const float*)d_in[12];
    const float* b2 = (const float*)d_in[13];
    const float* fb_ctx = (const float*)d_in[14];
    const float* fb_sum = (const float*)d_in[15];

    float* out = (float*)d_out;
    float* out_ctx  = out;
    float* out_sum  = out + (size_t)RB*RD;
    float* out_used = out + (size_t)RB*RD + (size_t)RB*RC;

    float *d_qn, *d_kn;
    __nv_bfloat16 *d_qh, *d_kh;
    cudaGetSymbolAddress((void**)&d_qn, g_qn);
    cudaGetSymbolAddress((void**)&d_kn, g_kn);
    cudaGetSymbolAddress((void**)&d_qh, g_qh);
    cudaGetSymbolAddress((void**)&d_kh, g_kh);

    proj_kernel<<<RB/KP_ROWS, 128>>>(current_repr, Wq, bq, d_qn, d_qh, RB);
    proj_kernel<<<(RM+KP_ROWS-1)/KP_ROWS, 128>>>(feature_q, Wk, bk, d_kn, d_kh, RM);
    dim3 sg(RMP/128, RB/128);
    sims_mma_kernel<<<sg, 256>>>(session_ids, session_q);
    topsel_kernel<<<RB, 256>>>();
    w1split_kernel<<<(RC*RC+255)/256, 256>>>(W1);
    refine_kernel<<<RB, 256>>>();
    attn_ctx_kernel<<<RB, RD>>>(feature_q, target_q, fb_ctx, out_ctx, out_used);
    dim3 g1(RC/128, RNR/128);
    gemm1_mma_kernel<<<g1, 256>>>(feature_q, item_emb, b1);
    reduce_kernel<<<RB, RC>>>();
    gemm2_kernel<<<RB, RC>>>(W2, b2, fb_sum, out_sum);
}